// round 3
// baseline (speedup 1.0000x reference)
#include <cuda_runtime.h>

#define BB 65536
#define DD 8
#define HH 128
#define EE 64

typedef unsigned long long ull;

__device__ __forceinline__ ull ffma2(ull a, ull b, ull c) {
    ull d;
    asm("fma.rn.f32x2 %0,%1,%2,%3;" : "=l"(d) : "l"(a), "l"(b), "l"(c));
    return d;
}
__device__ __forceinline__ ull pk2(float lo, float hi) {
    ull r;
    asm("mov.b64 %0,{%1,%2};" : "=l"(r) : "f"(lo), "f"(hi));
    return r;
}
__device__ __forceinline__ float2 upk(ull v) {
    float2 r;
    asm("mov.b64 {%0,%1},%2;" : "=f"(r.x), "=f"(r.y) : "l"(v));
    return r;
}

// ---------------- scratch ---------------------------------------------------
__device__ float g_tok[BB * DD * EE];   // [b][d][o]
__device__ float g_poolA[BB * EE];
__device__ float g_poolB[BB * EE];

// ---------------- Kernel A: tokens = W3 sin(W2 sin(x*w1+b1)+b2)+b3 ----------
// smem floats: sW2t 16384 + sW3t 8192 + sh1d 16384 + sh2d 16384 + 448 + 64
#define TOK_SMEM_F (16384 + 8192 + 16384 + 16384 + 128 * 3 + 64 + 64)

__global__ __launch_bounds__(512, 1)
void tok_kernel(const float* __restrict__ x,
                const float* __restrict__ w1, const float* __restrict__ b1,
                const float* __restrict__ w2, const float* __restrict__ b2,
                const float* __restrict__ w3, const float* __restrict__ b3)
{
    extern __shared__ float smem[];
    float* sW2t = smem;                 // [h][k] 128x128
    float* sW3t = sW2t + 16384;         // [h][o] 128x64
    float* sh1d = sW3t + 8192;          // [r][2h] 64x256 duplicated
    float* sh2d = sh1d + 16384;         // [r][2k] 64x256 duplicated
    float* sw1c = sh2d + 16384;         // 128
    float* sb1c = sw1c + 128;
    float* sb2c = sb1c + 128;
    float* sb3c = sb2c + 128;           // 64
    float* sx   = sb3c + 64;            // 64

    const int d   = blockIdx.y;
    const int tid = threadIdx.x;

    for (int i = tid; i < HH * HH; i += 512) {
        int k = i >> 7, h = i & 127;
        sW2t[h * HH + k] = w2[d * HH * HH + i];
    }
    for (int i = tid; i < EE * HH; i += 512) {
        int o = i >> 7, h = i & 127;
        sW3t[h * EE + o] = w3[d * EE * HH + i];
    }
    if (tid < 128) {
        sw1c[tid] = w1[d * HH + tid];
        sb1c[tid] = b1[d * HH + tid];
        sb2c[tid] = b2[d * HH + tid];
    }
    if (tid < 64) sb3c[tid] = b3[d * EE + tid];

    const int tx  = tid & 31;   // GEMM1: cols 4tx..4tx+3 (of 128)
    const int ty  = tid >> 5;   // GEMM1: rows 4ty..4ty+3 (of 64)
    const int tx2 = tid & 15;   // GEMM2: cols 4tx2..4tx2+3 (of 64)
    const int ty2 = tid >> 4;   // GEMM2: rows 2ty2..2ty2+1 (of 64)

    const int ntiles = BB / 64;
    for (int t = blockIdx.x; t < ntiles; t += gridDim.x) {
        const int r0 = t * 64;
        __syncthreads();   // prev-iter GEMM2 done reading sh2d / weights staged
        if (tid < 64) sx[tid] = x[(r0 + tid) * DD + d];
        __syncthreads();

        // h1 = sin(x*w1+b1), stored duplicated [r][2h]
        for (int i = tid; i < 64 * HH; i += 512) {
            int h = i & 127, r = i >> 7;
            float v = __sinf(sx[r] * sw1c[h] + sb1c[h]);
            *(float2*)(sh1d + r * 256 + 2 * h) = make_float2(v, v);
        }
        __syncthreads();

        // GEMM1: h2 = sin(W2 h1 + b2)  (f32x2, cols packed)
        {
            ull acc[4][2];
            #pragma unroll
            for (int j = 0; j < 4; j++) { acc[j][0] = 0ull; acc[j][1] = 0ull; }

            const float* a0 = sh1d + (4 * ty) * 256;
            #pragma unroll 4
            for (int h = 0; h < HH; h++) {
                ulonglong2 b = *(const ulonglong2*)(sW2t + h * HH + 4 * tx);
                #pragma unroll
                for (int j = 0; j < 4; j++) {
                    ull a = *(const ull*)(a0 + j * 256 + 2 * h);
                    acc[j][0] = ffma2(a, b.x, acc[j][0]);
                    acc[j][1] = ffma2(a, b.y, acc[j][1]);
                }
            }
            float bb0 = sb2c[4 * tx + 0], bb1 = sb2c[4 * tx + 1];
            float bb2 = sb2c[4 * tx + 2], bb3 = sb2c[4 * tx + 3];
            #pragma unroll
            for (int j = 0; j < 4; j++) {
                float2 p0 = upk(acc[j][0]);
                float2 p1 = upk(acc[j][1]);
                float v0 = __sinf(p0.x + bb0);
                float v1 = __sinf(p0.y + bb1);
                float v2 = __sinf(p1.x + bb2);
                float v3 = __sinf(p1.y + bb3);
                float* dst = sh2d + (4 * ty + j) * 256 + 8 * tx;
                *(float4*)(dst)     = make_float4(v0, v0, v1, v1);
                *(float4*)(dst + 4) = make_float4(v2, v2, v3, v3);
            }
        }
        __syncthreads();

        // GEMM2: tokens = W3 h2 + b3 -> global (f32x2)
        {
            ull acc2[2][2];
            ull bi0 = pk2(sb3c[4 * tx2 + 0], sb3c[4 * tx2 + 1]);
            ull bi1 = pk2(sb3c[4 * tx2 + 2], sb3c[4 * tx2 + 3]);
            acc2[0][0] = bi0; acc2[0][1] = bi1;
            acc2[1][0] = bi0; acc2[1][1] = bi1;

            const float* a0 = sh2d + (2 * ty2) * 256;
            #pragma unroll 4
            for (int h = 0; h < HH; h++) {
                ulonglong2 b = *(const ulonglong2*)(sW3t + h * EE + 4 * tx2);
                ull a0v = *(const ull*)(a0 + 2 * h);
                ull a1v = *(const ull*)(a0 + 256 + 2 * h);
                acc2[0][0] = ffma2(a0v, b.x, acc2[0][0]);
                acc2[0][1] = ffma2(a0v, b.y, acc2[0][1]);
                acc2[1][0] = ffma2(a1v, b.x, acc2[1][0]);
                acc2[1][1] = ffma2(a1v, b.y, acc2[1][1]);
            }
            #pragma unroll
            for (int j = 0; j < 2; j++) {
                int row = 2 * ty2 + j;
                float2 p0 = upk(acc2[j][0]);
                float2 p1 = upk(acc2[j][1]);
                *(float4*)(g_tok + ((r0 + row) * DD + d) * EE + 4 * tx2) =
                    make_float4(p0.x, p0.y, p1.x, p1.y);
            }
        }
    }
}

// ---------------- MHA: block-tile of 16 rows, f32x2 GEMM projections --------
#define MR 16
#define SQ 68
// smem floats: sWT 12288 + sWoT 4096 + sbin 192 + sbo 64 + tokd 16384
//            + sq/sk/sv 3*4352 + satt 1024 + sosd 2048  = 49152
#define MHA_SMEM_F 49152

template<int QOFF, int KVOFF, bool ACCUM, bool POOLB>
__global__ __launch_bounds__(256, 1)
void mha_kernel(const float* __restrict__ Win, const float* __restrict__ bin,
                const float* __restrict__ Wo,  const float* __restrict__ bo)
{
    extern __shared__ float smem[];
    float* sWT  = smem;                  // [c][e]  64x192
    float* sWoT = sWT + 12288;           // [c][e]  64x64
    float* sbin = sWoT + 4096;           // 192
    float* sbo  = sbin + 192;            // 64
    float* tokd = sbo + 64;              // [r][t][128] dup
    float* sq   = tokd + 16384;          // [r][4][68]
    float* sk   = sq + MR * 4 * SQ;
    float* sv   = sk + MR * 4 * SQ;
    float* satt = sv + MR * 4 * SQ;      // [r][64]
    float* sosd = satt + MR * 64;        // [r][128] dup

    const int tid = threadIdx.x;
    const int w = tid >> 5, l = tid & 31;
    const int txe = tid & 15, tyr = tid >> 4;

    for (int i = tid; i < 12288; i += 256) {
        int c = i / 192, e = i % 192;
        sWT[i] = Win[e * 64 + c];          // sWT[c*192+e]
    }
    for (int i = tid; i < 4096; i += 256) {
        int c = i >> 6, e = i & 63;
        sWoT[i] = Wo[e * 64 + c];
    }
    if (tid < 192) sbin[tid] = bin[tid];
    if (tid < 64)  sbo[tid]  = bo[tid];

    constexpr int NT = (QOFF == KVOFF) ? 4 : 8;
    constexpr int TBASE = (QOFF == KVOFF) ? QOFF : 0;

    float* pool = POOLB ? g_poolB : g_poolA;

    const int ntiles = BB / MR;
    for (int t = blockIdx.x; t < ntiles; t += gridDim.x) {
        const int r0 = t * MR;
        __syncthreads();  // prev tile fully consumed

        // load tokens (dup-stored)
        for (int idx = tid; idx < MR * NT * 16; idx += 256) {
            int c4 = idx & 15;
            int rest = idx >> 4;
            int tsel = TBASE + (rest % NT);
            int r = rest / NT;
            float4 v = *(const float4*)(g_tok + (r0 + r) * 512 + tsel * 64 + 4 * c4);
            float* dst = tokd + (r * 8 + tsel) * 128 + 8 * c4;
            *(float4*)(dst)     = make_float4(v.x, v.x, v.y, v.y);
            *(float4*)(dst + 4) = make_float4(v.z, v.z, v.w, v.w);
        }
        __syncthreads();

        // ---- projections: 3 GEMMs 64x64x64 ----
        #pragma unroll
        for (int mat = 0; mat < 3; mat++) {
            const int TOFF = (mat == 0) ? QOFF : KVOFF;
            float* dest = (mat == 0) ? sq : (mat == 1) ? sk : sv;

            const float* ap[4];
            #pragma unroll
            for (int j = 0; j < 4; j++) {
                int m = 4 * tyr + j;
                ap[j] = tokd + ((m >> 2) * 8 + TOFF + (m & 3)) * 128;
            }
            ull bi0 = pk2(sbin[mat * 64 + 4 * txe + 0], sbin[mat * 64 + 4 * txe + 1]);
            ull bi1 = pk2(sbin[mat * 64 + 4 * txe + 2], sbin[mat * 64 + 4 * txe + 3]);
            ull acc[4][2];
            #pragma unroll
            for (int j = 0; j < 4; j++) { acc[j][0] = bi0; acc[j][1] = bi1; }

            #pragma unroll 4
            for (int c = 0; c < 64; c++) {
                ulonglong2 b = *(const ulonglong2*)(sWT + c * 192 + mat * 64 + 4 * txe);
                #pragma unroll
                for (int j = 0; j < 4; j++) {
                    ull a = *(const ull*)(ap[j] + 2 * c);
                    acc[j][0] = ffma2(a, b.x, acc[j][0]);
                    acc[j][1] = ffma2(a, b.y, acc[j][1]);
                }
            }
            #pragma unroll
            for (int j = 0; j < 4; j++) {
                int m = 4 * tyr + j;
                float* dst = dest + (m >> 2) * (4 * SQ) + (m & 3) * SQ + 4 * txe;
                *(float2*)(dst)     = upk(acc[j][0]);
                *(float2*)(dst + 2) = upk(acc[j][1]);
            }
        }
        __syncthreads();

        // ---- attention: warp handles 2 rows ----
        #pragma unroll
        for (int rr = 0; rr < 2; rr++) {
            int row = 2 * w + rr;
            const float* sq_r = sq + row * (4 * SQ);
            const float* sk_r = sk + row * (4 * SQ);
            const float* sv_r = sv + row * (4 * SQ);
            float* satt_r = satt + row * 64;

            float a01[2];
            #pragma unroll
            for (int z = 0; z < 2; z++) {
                int m = l + 32 * z;
                int h = m >> 4, i = (m >> 2) & 3, j = m & 3;
                float dot = 0.f;
                #pragma unroll
                for (int dd2 = 0; dd2 < 16; dd2++)
                    dot += sq_r[i * SQ + h * 16 + dd2] * sk_r[j * SQ + h * 16 + dd2];
                a01[z] = dot * 0.25f;
            }
            float m0 = a01[0], m1 = a01[1];
            m0 = fmaxf(m0, __shfl_xor_sync(0xffffffffu, m0, 1));
            m0 = fmaxf(m0, __shfl_xor_sync(0xffffffffu, m0, 2));
            m1 = fmaxf(m1, __shfl_xor_sync(0xffffffffu, m1, 1));
            m1 = fmaxf(m1, __shfl_xor_sync(0xffffffffu, m1, 2));
            float e0 = __expf(a01[0] - m0), e1 = __expf(a01[1] - m1);
            float s0 = e0, s1 = e1;
            s0 += __shfl_xor_sync(0xffffffffu, s0, 1);
            s0 += __shfl_xor_sync(0xffffffffu, s0, 2);
            s1 += __shfl_xor_sync(0xffffffffu, s1, 1);
            s1 += __shfl_xor_sync(0xffffffffu, s1, 2);
            satt_r[l]      = __fdividef(e0, s0);
            satt_r[l + 32] = __fdividef(e1, s1);
            __syncwarp();

            float os0 = 0.f, os1 = 0.f;
            int h0 = l >> 4, h1 = h0 + 2;
            #pragma unroll
            for (int j = 0; j < 4; j++) {
                float wj0 = satt_r[h0 * 16 + j] + satt_r[h0 * 16 + 4 + j] +
                            satt_r[h0 * 16 + 8 + j] + satt_r[h0 * 16 + 12 + j];
                float wj1 = satt_r[h1 * 16 + j] + satt_r[h1 * 16 + 4 + j] +
                            satt_r[h1 * 16 + 8 + j] + satt_r[h1 * 16 + 12 + j];
                os0 += wj0 * sv_r[j * SQ + l];
                os1 += wj1 * sv_r[j * SQ + l + 32];
            }
            *(float2*)(sosd + row * 128 + 2 * l)        = make_float2(os0, os0);
            *(float2*)(sosd + row * 128 + 2 * (l + 32)) = make_float2(os1, os1);
        }
        __syncthreads();

        // ---- pooled out-projection ----
        {
            int r = tyr;
            ull acc0 = pk2(4.f * sbo[4 * txe + 0], 4.f * sbo[4 * txe + 1]);
            ull acc1 = pk2(4.f * sbo[4 * txe + 2], 4.f * sbo[4 * txe + 3]);
            const float* ar = sosd + r * 128;
            #pragma unroll 4
            for (int c = 0; c < 64; c++) {
                ulonglong2 b = *(const ulonglong2*)(sWoT + c * 64 + 4 * txe);
                ull a = *(const ull*)(ar + 2 * c);
                acc0 = ffma2(a, b.x, acc0);
                acc1 = ffma2(a, b.y, acc1);
            }
            float2 p0 = upk(acc0), p1 = upk(acc1);
            float4 v = make_float4(p0.x * 0.125f, p0.y * 0.125f,
                                   p1.x * 0.125f, p1.y * 0.125f);
            float* pp = pool + (r0 + r) * 64 + 4 * txe;
            if (ACCUM) {
                float4 old = *(const float4*)pp;
                v.x += old.x; v.y += old.y; v.z += old.z; v.w += old.w;
            }
            *(float4*)pp = v;
        }
    }
}

// ---------------- final ----------------------------------------------------
__global__ __launch_bounds__(256)
void final_kernel(const float* __restrict__ Wf, const float* __restrict__ bf,
                  float* __restrict__ out)
{
    int b = blockIdx.x * blockDim.x + threadIdx.x;
    if (b >= BB) return;
    const float4* pa = (const float4*)(g_poolA + b * 64);
    const float4* pb = (const float4*)(g_poolB + b * 64);
    float s = bf[0];
    #pragma unroll
    for (int i = 0; i < 16; i++) {
        float4 v = pa[i];
        float4 wv = *(const float4*)(Wf + 4 * i);
        s += v.x * wv.x + v.y * wv.y + v.z * wv.z + v.w * wv.w;
    }
    #pragma unroll
    for (int i = 0; i < 16; i++) {
        float4 v = pb[i];
        float4 wv = *(const float4*)(Wf + 64 + 4 * i);
        s += v.x * wv.x + v.y * wv.y + v.z * wv.z + v.w * wv.w;
    }
    out[b] = (s > 0.f) ? s : 0.01f * s;
}

// ---------------- launch ----------------------------------------------------
static const int A_SMEM = TOK_SMEM_F * 4;     // 231424 B
static const int M_SMEM = MHA_SMEM_F * 4;     // 196608 B

extern "C" void kernel_launch(void* const* d_in, const int* in_sizes, int n_in,
                              void* d_out, int out_size)
{
    (void)in_sizes; (void)n_in; (void)out_size;
    const float* x  = (const float*)d_in[0];
    const float* w1 = (const float*)d_in[1];
    const float* b1 = (const float*)d_in[2];
    const float* w2 = (const float*)d_in[3];
    const float* b2 = (const float*)d_in[4];
    const float* w3 = (const float*)d_in[5];
    const float* b3 = (const float*)d_in[6];
    const float* Win_sa = (const float*)d_in[7];
    const float* bin_sa = (const float*)d_in[8];
    const float* Wo_sa  = (const float*)d_in[9];
    const float* bo_sa  = (const float*)d_in[10];
    const float* Win_sb = (const float*)d_in[11];
    const float* bin_sb = (const float*)d_in[12];
    const float* Wo_sb  = (const float*)d_in[13];
    const float* bo_sb  = (const float*)d_in[14];
    const float* Win_ca = (const float*)d_in[15];
    const float* bin_ca = (const float*)d_in[16];
    const float* Wo_ca  = (const float*)d_in[17];
    const float* bo_ca  = (const float*)d_in[18];
    const float* Win_cb = (const float*)d_in[19];
    const float* bin_cb = (const float*)d_in[20];
    const float* Wo_cb  = (const float*)d_in[21];
    const float* bo_cb  = (const float*)d_in[22];
    const float* Wf = (const float*)d_in[23];
    const float* bf = (const float*)d_in[24];
    float* out = (float*)d_out;

    cudaFuncSetAttribute(tok_kernel, cudaFuncAttributeMaxDynamicSharedMemorySize, A_SMEM);
    cudaFuncSetAttribute(mha_kernel<0, 0, false, false>, cudaFuncAttributeMaxDynamicSharedMemorySize, M_SMEM);
    cudaFuncSetAttribute(mha_kernel<4, 4, false, true>,  cudaFuncAttributeMaxDynamicSharedMemorySize, M_SMEM);
    cudaFuncSetAttribute(mha_kernel<0, 4, true,  false>, cudaFuncAttributeMaxDynamicSharedMemorySize, M_SMEM);
    cudaFuncSetAttribute(mha_kernel<4, 0, true,  true>,  cudaFuncAttributeMaxDynamicSharedMemorySize, M_SMEM);

    tok_kernel<<<dim3(18, 8), 512, A_SMEM>>>(x, w1, b1, w2, b2, w3, b3);

    mha_kernel<0, 0, false, false><<<148, 256, M_SMEM>>>(Win_sa, bin_sa, Wo_sa, bo_sa);
    mha_kernel<4, 4, false, true ><<<148, 256, M_SMEM>>>(Win_sb, bin_sb, Wo_sb, bo_sb);
    mha_kernel<0, 4, true,  false><<<148, 256, M_SMEM>>>(Win_ca, bin_ca, Wo_ca, bo_ca);
    mha_kernel<4, 0, true,  true ><<<148, 256, M_SMEM>>>(Win_cb, bin_cb, Wo_cb, bo_cb);

    final_kernel<<<BB / 256, 256>>>(Wf, bf, out);
}

// round 5
// speedup vs baseline: 1.0532x; 1.0532x over previous
#include <cuda_runtime.h>

#define BB 65536
#define DD 8
#define HH 128
#define EE 64

typedef unsigned long long ull;

__device__ __forceinline__ ull ffma2(ull a, ull b, ull c) {
    ull d;
    asm("fma.rn.f32x2 %0,%1,%2,%3;" : "=l"(d) : "l"(a), "l"(b), "l"(c));
    return d;
}
__device__ __forceinline__ ull pk2(float lo, float hi) {
    ull r;
    asm("mov.b64 %0,{%1,%2};" : "=l"(r) : "f"(lo), "f"(hi));
    return r;
}
__device__ __forceinline__ float2 upk(ull v) {
    float2 r;
    asm("mov.b64 {%0,%1},%2;" : "=f"(r.x), "=f"(r.y) : "l"(v));
    return r;
}
__device__ __forceinline__ ull ld2(const float* p) {
    return *(const ull*)p;
}

// ---------------- scratch ---------------------------------------------------
__device__ float g_tok[BB * DD * EE];   // [b][d(token)][o]
__device__ float g_poolA[BB * EE];
__device__ float g_poolB[BB * EE];

// ============================================================================
// Kernel A: tokens = W3 sin(W2 sin(x*w1+b1)+b2)+b3
// 512 threads, grid (37, 8). K-packed f32x2, native layouts, stride-130 pad.
// ============================================================================
#define ST 130
#define TOK_SMEM_F (128*ST + 64*ST + 64*ST + 64*ST + 128*3 + 64 + 64)  // 42112

__global__ __launch_bounds__(512, 1)
void tok_kernel(const float* __restrict__ x,
                const float* __restrict__ w1, const float* __restrict__ b1,
                const float* __restrict__ w2, const float* __restrict__ b2,
                const float* __restrict__ w3, const float* __restrict__ b3)
{
    extern __shared__ float sm[];
    float* sW2  = sm;                    // [k][h] native, stride 130
    float* sW3  = sW2 + 128 * ST;        // [o][h] native, stride 130
    float* sh1  = sW3 + 64 * ST;         // [r][h] stride 130
    float* sh2  = sh1 + 64 * ST;         // [r][k] stride 130
    float* sw1c = sh2 + 64 * ST;         // 128
    float* sb1c = sw1c + 128;
    float* sb2c = sb1c + 128;
    float* sb3c = sb2c + 128;            // 64
    float* sx   = sb3c + 64;             // 64

    const int d   = blockIdx.y;
    const int tid = threadIdx.x;
    const int wid = tid >> 5, lane = tid & 31;
    const int kl  = lane & 15, sg = lane >> 4;
    const int rbase = wid * 4 + sg * 2;  // this thread covers rows rbase, rbase+1

    for (int i = tid; i < HH * HH; i += 512) {
        int k = i >> 7, h = i & 127;
        sW2[k * ST + h] = w2[d * HH * HH + i];
    }
    for (int i = tid; i < EE * HH; i += 512) {
        int o = i >> 7, h = i & 127;
        sW3[o * ST + h] = w3[d * EE * HH + i];
    }
    if (tid < 128) {
        sw1c[tid] = w1[d * HH + tid];
        sb1c[tid] = b1[d * HH + tid];
        sb2c[tid] = b2[d * HH + tid];
    }
    if (tid < 64) sb3c[tid] = b3[d * EE + tid];

    for (int t = blockIdx.x; t < BB / 64; t += gridDim.x) {
        const int r0 = t * 64;
        __syncthreads();                 // prev-iter consumers done
        if (tid < 64) sx[tid] = x[(r0 + tid) * DD + d];
        __syncthreads();

        // h1 = sin(x*w1+b1)
        for (int i = tid; i < 64 * HH; i += 512) {
            int r = i >> 7, h = i & 127;
            sh1[r * ST + h] = __sinf(sx[r] * sw1c[h] + sb1c[h]);
        }
        __syncthreads();

        // GEMM1: h2[r][k] = sin(sum_h W2[k][h] h1[r][h] + b2[k])
        // thread: rows {rbase, rbase+1} x k in {kl+16j, j<8}
        {
            ull acc[2][8];
            #pragma unroll
            for (int i = 0; i < 2; i++)
                #pragma unroll
                for (int j = 0; j < 8; j++) acc[i][j] = 0ull;

            const float* a0 = sh1 + rbase * ST;
            const float* a1 = a0 + ST;
            const float* bp = sW2 + kl * ST;
            #pragma unroll 4
            for (int h = 0; h < HH; h += 2) {
                ull av0 = ld2(a0 + h);
                ull av1 = ld2(a1 + h);
                #pragma unroll
                for (int j = 0; j < 8; j++) {
                    ull bv = ld2(bp + j * 16 * ST + h);
                    acc[0][j] = ffma2(av0, bv, acc[0][j]);
                    acc[1][j] = ffma2(av1, bv, acc[1][j]);
                }
            }
            #pragma unroll
            for (int i = 0; i < 2; i++)
                #pragma unroll
                for (int j = 0; j < 8; j++) {
                    float2 p = upk(acc[i][j]);
                    int k = kl + 16 * j;
                    sh2[(rbase + i) * ST + k] = __sinf(p.x + p.y + sb2c[k]);
                }
        }
        __syncthreads();

        // GEMM2: tok[r][o] = sum_h W3[o][h] h2[r][h] + b3[o]
        {
            ull acc[2][4];
            #pragma unroll
            for (int i = 0; i < 2; i++)
                #pragma unroll
                for (int j = 0; j < 4; j++) acc[i][j] = pk2(sb3c[kl + 16 * j], 0.f);

            const float* a0 = sh2 + rbase * ST;
            const float* a1 = a0 + ST;
            const float* bp = sW3 + kl * ST;
            #pragma unroll 4
            for (int h = 0; h < HH; h += 2) {
                ull av0 = ld2(a0 + h);
                ull av1 = ld2(a1 + h);
                #pragma unroll
                for (int j = 0; j < 4; j++) {
                    ull bv = ld2(bp + j * 16 * ST + h);
                    acc[0][j] = ffma2(av0, bv, acc[0][j]);
                    acc[1][j] = ffma2(av1, bv, acc[1][j]);
                }
            }
            #pragma unroll
            for (int i = 0; i < 2; i++)
                #pragma unroll
                for (int j = 0; j < 4; j++) {
                    float2 p = upk(acc[i][j]);
                    g_tok[((r0 + rbase + i) * DD + d) * EE + kl + 16 * j] = p.x + p.y;
                }
        }
    }
}

// ============================================================================
// MHA: 256 threads, 8 rows/tile, 2 blocks/SM. K-packed f32x2, stride-66 pad.
// ============================================================================
#define SW 66
#define MHA_SMEM_F (192*SW + 64*SW + 192 + 64 + 8*8*SW + 3*8*4*SW + 512 + 8*SW) // 28752

template<int QOFF, int KVOFF, bool ACCUM, bool POOLB>
__global__ __launch_bounds__(256, 2)
void mha_kernel(const float* __restrict__ Win, const float* __restrict__ bin,
                const float* __restrict__ Wo,  const float* __restrict__ bo)
{
    extern __shared__ float sm[];
    float* sWin = sm;                    // [e][c] native, stride 66 (192 rows)
    float* sWo  = sWin + 192 * SW;       // [e][c] native
    float* sbin = sWo + 64 * SW;         // 192
    float* sbo  = sbin + 192;            // 64
    float* stok = sbo + 64;              // [r][tok][c] stride 66 (up to 8x8)
    float* sq   = stok + 8 * 8 * SW;     // [r][4][66]
    float* sk   = sq + 8 * 4 * SW;
    float* sv   = sk + 8 * 4 * SW;
    float* satt = sv + 8 * 4 * SW;       // [r][64]
    float* sos  = satt + 512;            // [r][66]

    const int tid = threadIdx.x;
    const int wid = tid >> 5, lane = tid & 31;
    const int kl  = lane & 15, sg = lane >> 4;

    constexpr bool SELF = (QOFF == KVOFF);

    for (int i = tid; i < 192 * 64; i += 256) {
        int e = i >> 6, c = i & 63;
        sWin[e * SW + c] = Win[i];
    }
    for (int i = tid; i < 64 * 64; i += 256) {
        int e = i >> 6, c = i & 63;
        sWo[e * SW + c] = Wo[i];
    }
    if (tid < 192) sbin[tid] = bin[tid];
    if (tid < 64)  sbo[tid]  = bo[tid];

    float* pool = POOLB ? g_poolB : g_poolA;
    const int tk0 = sg * 2;          // this thread's two token slots

    for (int t = blockIdx.x; t < BB / 8; t += gridDim.x) {
        const int r0 = t * 8;
        __syncthreads();             // prev tile fully consumed

        if (SELF) {
            for (int i = tid; i < 2048; i += 256) {
                int r = i >> 8, tk = (i >> 6) & 3, c = i & 63;
                stok[(r * 4 + tk) * SW + c] =
                    g_tok[(r0 + r) * 512 + (QOFF + tk) * 64 + c];
            }
        } else {
            for (int i = tid; i < 4096; i += 256) {
                int r = i >> 9, tk = (i >> 6) & 7, c = i & 63;
                stok[(r * 8 + tk) * SW + c] =
                    g_tok[(r0 + r) * 512 + tk * 64 + c];
            }
        }
        __syncthreads();

        // ---- projections (warp wid owns row wid; lanes cover e) ----
        if (SELF) {
            // one GEMM: 4 tokens x 192 outputs, K=64
            ull acc[2][12];
            #pragma unroll
            for (int i = 0; i < 2; i++)
                #pragma unroll
                for (int j = 0; j < 12; j++) acc[i][j] = pk2(sbin[kl + 16 * j], 0.f);

            const float* a0 = stok + (wid * 4 + tk0) * SW;
            const float* a1 = a0 + SW;
            const float* bp = sWin + kl * SW;
            #pragma unroll 2
            for (int c = 0; c < 64; c += 2) {
                ull av0 = ld2(a0 + c);
                ull av1 = ld2(a1 + c);
                #pragma unroll
                for (int j = 0; j < 12; j++) {
                    ull bv = ld2(bp + j * 16 * SW + c);
                    acc[0][j] = ffma2(av0, bv, acc[0][j]);
                    acc[1][j] = ffma2(av1, bv, acc[1][j]);
                }
            }
            #pragma unroll
            for (int i = 0; i < 2; i++) {
                int row = (wid * 4 + tk0 + i) * SW;
                #pragma unroll
                for (int j = 0; j < 12; j++) {
                    float2 p = upk(acc[i][j]);
                    float v = p.x + p.y;
                    int e2 = kl + 16 * (j & 3);
                    if (j < 4)      sq[row + e2] = v;
                    else if (j < 8) sk[row + e2] = v;
                    else            sv[row + e2] = v;
                }
            }
        } else {
            // Q: 4 tokens x 64 outputs
            {
                ull acc[2][4];
                #pragma unroll
                for (int i = 0; i < 2; i++)
                    #pragma unroll
                    for (int j = 0; j < 4; j++) acc[i][j] = pk2(sbin[kl + 16 * j], 0.f);
                const float* a0 = stok + (wid * 8 + QOFF + tk0) * SW;
                const float* a1 = a0 + SW;
                const float* bp = sWin + kl * SW;
                #pragma unroll 4
                for (int c = 0; c < 64; c += 2) {
                    ull av0 = ld2(a0 + c);
                    ull av1 = ld2(a1 + c);
                    #pragma unroll
                    for (int j = 0; j < 4; j++) {
                        ull bv = ld2(bp + j * 16 * SW + c);
                        acc[0][j] = ffma2(av0, bv, acc[0][j]);
                        acc[1][j] = ffma2(av1, bv, acc[1][j]);
                    }
                }
                #pragma unroll
                for (int i = 0; i < 2; i++) {
                    int row = (wid * 4 + tk0 + i) * SW;
                    #pragma unroll
                    for (int j = 0; j < 4; j++) {
                        float2 p = upk(acc[i][j]);
                        sq[row + kl + 16 * j] = p.x + p.y;
                    }
                }
            }
            // K,V: 4 tokens x 128 outputs
            {
                ull acc[2][8];
                #pragma unroll
                for (int i = 0; i < 2; i++)
                    #pragma unroll
                    for (int j = 0; j < 8; j++) acc[i][j] = pk2(sbin[64 + kl + 16 * j], 0.f);
                const float* a0 = stok + (wid * 8 + KVOFF + tk0) * SW;
                const float* a1 = a0 + SW;
                const float* bp = sWin + (64 + kl) * SW;
                #pragma unroll 2
                for (int c = 0; c < 64; c += 2) {
                    ull av0 = ld2(a0 + c);
                    ull av1 = ld2(a1 + c);
                    #pragma unroll
                    for (int j = 0; j < 8; j++) {
                        ull bv = ld2(bp + j * 16 * SW + c);
                        acc[0][j] = ffma2(av0, bv, acc[0][j]);
                        acc[1][j] = ffma2(av1, bv, acc[1][j]);
                    }
                }
                #pragma unroll
                for (int i = 0; i < 2; i++) {
                    int row = (wid * 4 + tk0 + i) * SW;
                    #pragma unroll
                    for (int j = 0; j < 8; j++) {
                        float2 p = upk(acc[i][j]);
                        float v = p.x + p.y;
                        int e2 = kl + 16 * (j & 3);
                        if (j < 4) sk[row + e2] = v;
                        else       sv[row + e2] = v;
                    }
                }
            }
        }
        __syncthreads();

        // ---- attention: warp wid handles row wid ----
        {
            const float* sq_r = sq + wid * 4 * SW;
            const float* sk_r = sk + wid * 4 * SW;
            const float* sv_r = sv + wid * 4 * SW;
            float* satt_r = satt + wid * 64;

            float a01[2];
            #pragma unroll
            for (int z = 0; z < 2; z++) {
                int m = lane + 32 * z;
                int h = m >> 4, i = (m >> 2) & 3, j = m & 3;
                float dot = 0.f;
                #pragma unroll
                for (int dd2 = 0; dd2 < 16; dd2++)
                    dot += sq_r[i * SW + h * 16 + dd2] * sk_r[j * SW + h * 16 + dd2];
                a01[z] = dot * 0.25f;
            }
            float m0 = a01[0], m1 = a01[1];
            m0 = fmaxf(m0, __shfl_xor_sync(0xffffffffu, m0, 1));
            m0 = fmaxf(m0, __shfl_xor_sync(0xffffffffu, m0, 2));
            m1 = fmaxf(m1, __shfl_xor_sync(0xffffffffu, m1, 1));
            m1 = fmaxf(m1, __shfl_xor_sync(0xffffffffu, m1, 2));
            float e0 = __expf(a01[0] - m0), e1 = __expf(a01[1] - m1);
            float s0 = e0, s1 = e1;
            s0 += __shfl_xor_sync(0xffffffffu, s0, 1);
            s0 += __shfl_xor_sync(0xffffffffu, s0, 2);
            s1 += __shfl_xor_sync(0xffffffffu, s1, 1);
            s1 += __shfl_xor_sync(0xffffffffu, s1, 2);
            satt_r[lane]      = __fdividef(e0, s0);
            satt_r[lane + 32] = __fdividef(e1, s1);
            __syncwarp();

            float os0 = 0.f, os1 = 0.f;
            int h0 = lane >> 4, h1 = h0 + 2;
            #pragma unroll
            for (int j = 0; j < 4; j++) {
                float wj0 = satt_r[h0 * 16 + j] + satt_r[h0 * 16 + 4 + j] +
                            satt_r[h0 * 16 + 8 + j] + satt_r[h0 * 16 + 12 + j];
                float wj1 = satt_r[h1 * 16 + j] + satt_r[h1 * 16 + 4 + j] +
                            satt_r[h1 * 16 + 8 + j] + satt_r[h1 * 16 + 12 + j];
                os0 += wj0 * sv_r[j * SW + lane];
                os1 += wj1 * sv_r[j * SW + lane + 32];
            }
            sos[wid * SW + lane]      = os0;
            sos[wid * SW + lane + 32] = os1;
        }
        __syncthreads();

        // ---- pooled out-projection: warp wid -> row wid ----
        {
            int e0 = kl + 32 * sg;
            int e1 = e0 + 16;
            ull acc0 = pk2(4.f * sbo[e0], 0.f);
            ull acc1 = pk2(4.f * sbo[e1], 0.f);
            const float* ar = sos + wid * SW;
            const float* b0 = sWo + e0 * SW;
            const float* b1 = sWo + e1 * SW;
            #pragma unroll 4
            for (int c = 0; c < 64; c += 2) {
                ull av = ld2(ar + c);
                acc0 = ffma2(av, ld2(b0 + c), acc0);
                acc1 = ffma2(av, ld2(b1 + c), acc1);
            }
            float2 p0 = upk(acc0), p1 = upk(acc1);
            float v0 = (p0.x + p0.y) * 0.125f;
            float v1 = (p1.x + p1.y) * 0.125f;
            float* pp = pool + (r0 + wid) * 64;
            if (ACCUM) { pp[e0] += v0; pp[e1] += v1; }
            else       { pp[e0] = v0;  pp[e1] = v1; }
        }
    }
}

// ---------------- final ----------------------------------------------------
__global__ __launch_bounds__(256)
void final_kernel(const float* __restrict__ Wf, const float* __restrict__ bf,
                  float* __restrict__ out)
{
    int b = blockIdx.x * blockDim.x + threadIdx.x;
    if (b >= BB) return;
    const float4* pa = (const float4*)(g_poolA + b * 64);
    const float4* pb = (const float4*)(g_poolB + b * 64);
    float s = bf[0];
    #pragma unroll
    for (int i = 0; i < 16; i++) {
        float4 v = pa[i];
        float4 wv = *(const float4*)(Wf + 4 * i);
        s += v.x * wv.x + v.y * wv.y + v.z * wv.z + v.w * wv.w;
    }
    #pragma unroll
    for (int i = 0; i < 16; i++) {
        float4 v = pb[i];
        float4 wv = *(const float4*)(Wf + 64 + 4 * i);
        s += v.x * wv.x + v.y * wv.y + v.z * wv.z + v.w * wv.w;
    }
    out[b] = (s > 0.f) ? s : 0.01f * s;
}

// ---------------- launch ----------------------------------------------------
static const int A_SMEM = TOK_SMEM_F * 4;   // 168448 B
static const int M_SMEM = MHA_SMEM_F * 4;   // 115008 B

extern "C" void kernel_launch(void* const* d_in, const int* in_sizes, int n_in,
                              void* d_out, int out_size)
{
    (void)in_sizes; (void)n_in; (void)out_size;
    const float* x  = (const float*)d_in[0];
    const float* w1 = (const float*)d_in[1];
    const float* b1 = (const float*)d_in[2];
    const float* w2 = (const float*)d_in[3];
    const float* b2 = (const float*)d_in[4];
    const float* w3 = (const float*)d_in[5];
    const float* b3 = (const float*)d_in[6];
    const float* Win_sa = (const float*)d_in[7];
    const float* bin_sa = (const float*)d_in[8];
    const float* Wo_sa  = (const float*)d_in[9];
    const float* bo_sa  = (const float*)d_in[10];
    const float* Win_sb = (const float*)d_in[11];
    const float* bin_sb = (const float*)d_in[12];
    const float* Wo_sb  = (const float*)d_in[13];
    const float* bo_sb  = (const float*)d_in[14];
    const float* Win_ca = (const float*)d_in[15];
    const float* bin_ca = (const float*)d_in[16];
    const float* Wo_ca  = (const float*)d_in[17];
    const float* bo_ca  = (const float*)d_in[18];
    const float* Win_cb = (const float*)d_in[19];
    const float* bin_cb = (const float*)d_in[20];
    const float* Wo_cb  = (const float*)d_in[21];
    const float* bo_cb  = (const float*)d_in[22];
    const float* Wf = (const float*)d_in[23];
    const float* bf = (const float*)d_in[24];
    float* out = (float*)d_out;

    cudaFuncSetAttribute(tok_kernel, cudaFuncAttributeMaxDynamicSharedMemorySize, A_SMEM);
    cudaFuncSetAttribute(mha_kernel<0, 0, false, false>, cudaFuncAttributeMaxDynamicSharedMemorySize, M_SMEM);
    cudaFuncSetAttribute(mha_kernel<4, 4, false, true>,  cudaFuncAttributeMaxDynamicSharedMemorySize, M_SMEM);
    cudaFuncSetAttribute(mha_kernel<0, 4, true,  false>, cudaFuncAttributeMaxDynamicSharedMemorySize, M_SMEM);
    cudaFuncSetAttribute(mha_kernel<4, 0, true,  true>,  cudaFuncAttributeMaxDynamicSharedMemorySize, M_SMEM);

    tok_kernel<<<dim3(37, 8), 512, A_SMEM>>>(x, w1, b1, w2, b2, w3, b3);

    mha_kernel<0, 0, false, false><<<296, 256, M_SMEM>>>(Win_sa, bin_sa, Wo_sa, bo_sa);
    mha_kernel<4, 4, false, true ><<<296, 256, M_SMEM>>>(Win_sb, bin_sb, Wo_sb, bo_sb);
    mha_kernel<0, 4, true,  false><<<296, 256, M_SMEM>>>(Win_ca, bin_ca, Wo_ca, bo_ca);
    mha_kernel<4, 0, true,  true ><<<296, 256, M_SMEM>>>(Win_cb, bin_cb, Wo_cb, bo_cb);

    final_kernel<<<BB / 256, 256>>>(Wf, bf, out);
}

// round 6
// speedup vs baseline: 1.2887x; 1.2236x over previous
#include <cuda_runtime.h>

#define BB 65536
#define DD 8
#define HH 128
#define EE 64

typedef unsigned long long ull;

__device__ __forceinline__ ull ffma2(ull a, ull b, ull c) {
    ull d;
    asm("fma.rn.f32x2 %0,%1,%2,%3;" : "=l"(d) : "l"(a), "l"(b), "l"(c));
    return d;
}
__device__ __forceinline__ ull pk2(float lo, float hi) {
    ull r;
    asm("mov.b64 %0,{%1,%2};" : "=l"(r) : "f"(lo), "f"(hi));
    return r;
}
__device__ __forceinline__ float2 upk(ull v) {
    float2 r;
    asm("mov.b64 {%0,%1},%2;" : "=f"(r.x), "=f"(r.y) : "l"(v));
    return r;
}
__device__ __forceinline__ ull ld2(const float* p) {
    return *(const ull*)p;
}

// ---------------- scratch ---------------------------------------------------
__device__ float g_tok[BB * DD * EE];   // [b][token d][o]
__device__ float g_poolA[BB * EE];
__device__ float g_poolB[BB * EE];

// ============================================================================
// Kernel A: tokens = W3 sin(W2 sin(x*w1+b1)+b2)+b3
// 512 threads. Register-blocked 4-row f32x2, dedup'd weight loads.
// ============================================================================
#define ST 130
#define TOK_SMEM_F (128*ST + 64*ST + 64*ST + 64*ST + 128*3 + 64 + 64)  // 42112

__global__ __launch_bounds__(512, 1)
void tok_kernel(const float* __restrict__ x,
                const float* __restrict__ w1, const float* __restrict__ b1,
                const float* __restrict__ w2, const float* __restrict__ b2,
                const float* __restrict__ w3, const float* __restrict__ b3)
{
    extern __shared__ float sm[];
    float* sW2  = sm;                    // [k][h] native, stride 130
    float* sW3  = sW2 + 128 * ST;        // [o][h] native, stride 130
    float* sh1  = sW3 + 64 * ST;         // [r][h]
    float* sh2  = sh1 + 64 * ST;         // [r][k]
    float* sw1c = sh2 + 64 * ST;         // 128
    float* sb1c = sw1c + 128;
    float* sb2c = sb1c + 128;
    float* sb3c = sb2c + 128;            // 64
    float* sx   = sb3c + 64;             // 64

    const int d    = blockIdx.y;
    const int tid  = threadIdx.x;
    const int w    = tid >> 5, lane = tid & 31;
    const int kl   = lane & 15, sg = lane >> 4;
    const int eh   = w & 1;              // output half
    const int rgw  = w >> 1;             // 0..7
    const int tr0  = rgw * 8 + sg * 4;   // first of this thread's 4 rows

    for (int i = tid; i < HH * HH; i += 512) {
        int k = i >> 7, h = i & 127;
        sW2[k * ST + h] = w2[d * HH * HH + i];
    }
    for (int i = tid; i < EE * HH; i += 512) {
        int o = i >> 7, h = i & 127;
        sW3[o * ST + h] = w3[d * EE * HH + i];
    }
    if (tid < 128) {
        sw1c[tid] = w1[d * HH + tid];
        sb1c[tid] = b1[d * HH + tid];
        sb2c[tid] = b2[d * HH + tid];
    }
    if (tid < 64) sb3c[tid] = b3[d * EE + tid];

    for (int t = blockIdx.x; t < BB / 64; t += gridDim.x) {
        const int r0 = t * 64;
        __syncthreads();                 // prev-iter consumers done
        if (tid < 64) sx[tid] = x[(r0 + tid) * DD + d];
        __syncthreads();

        // h1 = sin(x*w1+b1)
        for (int i = tid; i < 64 * HH; i += 512) {
            int r = i >> 7, h = i & 127;
            sh1[r * ST + h] = __sinf(sx[r] * sw1c[h] + sb1c[h]);
        }
        __syncthreads();

        // GEMM1: h2[r][k] = sin(sum_h W2[k][h] h1[r][h] + b2[k])
        // thread: 4 rows (tr0..tr0+3) x 4 k (kl+16s+64eh)
        {
            ull acc[4][4];
            #pragma unroll
            for (int i = 0; i < 4; i++)
                #pragma unroll
                for (int s = 0; s < 4; s++) acc[i][s] = 0ull;

            const float* bp = sW2 + (kl + 64 * eh) * ST;
            const float* a0 = sh1 + tr0 * ST;
            #pragma unroll 4
            for (int h = 0; h < HH; h += 2) {
                ull bv[4];
                #pragma unroll
                for (int s = 0; s < 4; s++) bv[s] = ld2(bp + s * 16 * ST + h);
                #pragma unroll
                for (int i = 0; i < 4; i++) {
                    ull av = ld2(a0 + i * ST + h);
                    #pragma unroll
                    for (int s = 0; s < 4; s++)
                        acc[i][s] = ffma2(av, bv[s], acc[i][s]);
                }
            }
            #pragma unroll
            for (int i = 0; i < 4; i++)
                #pragma unroll
                for (int s = 0; s < 4; s++) {
                    float2 p = upk(acc[i][s]);
                    int k = kl + 16 * s + 64 * eh;
                    sh2[(tr0 + i) * ST + k] = __sinf(p.x + p.y + sb2c[k]);
                }
        }
        __syncthreads();

        // GEMM2: tok[r][o] = sum_h W3[o][h] h2[r][h] + b3[o]
        // thread: 4 rows x 2 o (kl+16s+32eh)
        {
            ull acc[4][2];
            #pragma unroll
            for (int i = 0; i < 4; i++)
                #pragma unroll
                for (int s = 0; s < 2; s++)
                    acc[i][s] = pk2(sb3c[kl + 16 * s + 32 * eh], 0.f);

            const float* bp = sW3 + (kl + 32 * eh) * ST;
            const float* a0 = sh2 + tr0 * ST;
            #pragma unroll 4
            for (int h = 0; h < HH; h += 2) {
                ull bv[2];
                #pragma unroll
                for (int s = 0; s < 2; s++) bv[s] = ld2(bp + s * 16 * ST + h);
                #pragma unroll
                for (int i = 0; i < 4; i++) {
                    ull av = ld2(a0 + i * ST + h);
                    #pragma unroll
                    for (int s = 0; s < 2; s++)
                        acc[i][s] = ffma2(av, bv[s], acc[i][s]);
                }
            }
            #pragma unroll
            for (int i = 0; i < 4; i++)
                #pragma unroll
                for (int s = 0; s < 2; s++) {
                    float2 p = upk(acc[i][s]);
                    int e = kl + 16 * s + 32 * eh;
                    g_tok[((r0 + tr0 + i) * DD + d) * EE + e] = p.x + p.y;
                }
        }
    }
}

// ============================================================================
// MHA: 256 threads, tile 8 batch rows, 2 blocks/SM.
// Register-blocked projections: thread = 4 token-rows x 6 outputs.
// ============================================================================
#define SW 66
#define MHA_SMEM_F (192*SW + 64*SW + 192 + 64 + 8*8*SW + 3*8*4*SW + 512 + 8*SW) // 28752

template<int QOFF, int KVOFF, bool ACCUM, bool POOLB>
__global__ __launch_bounds__(256, 2)
void mha_kernel(const float* __restrict__ Win, const float* __restrict__ bin,
                const float* __restrict__ Wo,  const float* __restrict__ bo)
{
    extern __shared__ float sm[];
    float* sWin = sm;                    // [e][c] native, stride 66 (192 rows)
    float* sWo  = sWin + 192 * SW;       // [e][c] native
    float* sbin = sWo + 64 * SW;         // 192
    float* sbo  = sbin + 192;            // 64
    float* stok = sbo + 64;              // [br][tok][c] stride 66 (8x8 max)
    float* sq   = stok + 8 * 8 * SW;     // [tr][66], tr = br*4+tk (32 rows)
    float* sk   = sq + 8 * 4 * SW;
    float* sv   = sk + 8 * 4 * SW;
    float* satt = sv + 8 * 4 * SW;       // [br][64]
    float* sos  = satt + 512;            // [br][66]

    const int tid  = threadIdx.x;
    const int w    = tid >> 5, lane = tid & 31;
    const int kl   = lane & 15, sg = lane >> 4;
    const int eh   = w & 1;              // e-half: e = kl + 16*s + 96*eh
    const int rgw  = w >> 1;             // 0..3
    const int tr0  = rgw * 8 + sg * 4;   // first of 4 token-rows (of 32)

    constexpr bool SELF = (QOFF == KVOFF);

    for (int i = tid; i < 192 * 64; i += 256) {
        int e = i >> 6, c = i & 63;
        sWin[e * SW + c] = Win[i];
    }
    for (int i = tid; i < 64 * 64; i += 256) {
        int e = i >> 6, c = i & 63;
        sWo[e * SW + c] = Wo[i];
    }
    if (tid < 192) sbin[tid] = bin[tid];
    if (tid < 64)  sbo[tid]  = bo[tid];

    float* pool = POOLB ? g_poolB : g_poolA;

    for (int t = blockIdx.x; t < BB / 8; t += gridDim.x) {
        const int r0 = t * 8;
        __syncthreads();             // prev tile fully consumed

        if (SELF) {
            for (int i = tid; i < 2048; i += 256) {
                int r = i >> 8, tk = (i >> 6) & 3, c = i & 63;
                stok[(r * 4 + tk) * SW + c] =
                    g_tok[(r0 + r) * 512 + (QOFF + tk) * 64 + c];
            }
        } else {
            for (int i = tid; i < 4096; i += 256) {
                int r = i >> 9, tk = (i >> 6) & 7, c = i & 63;
                stok[(r * 8 + tk) * SW + c] =
                    g_tok[(r0 + r) * 512 + tk * 64 + c];
            }
        }
        __syncthreads();

        // ---- projections: thread = 4 token-rows x 6 outputs --------------
        {
            ull acc[4][6];
            #pragma unroll
            for (int i = 0; i < 4; i++)
                #pragma unroll
                for (int s = 0; s < 6; s++)
                    acc[i][s] = pk2(sbin[kl + 16 * s + 96 * eh], 0.f);

            const float* aq[4];
            const float* ak[4];
            #pragma unroll
            for (int i = 0; i < 4; i++) {
                int tr = tr0 + i, br = tr >> 2, tk = tr & 3;
                if (SELF) {
                    aq[i] = stok + (br * 4 + tk) * SW;
                    ak[i] = aq[i];
                } else {
                    aq[i] = stok + (br * 8 + QOFF + tk) * SW;
                    ak[i] = stok + (br * 8 + KVOFF + tk) * SW;
                }
            }
            const float* bp = sWin + (kl + 96 * eh) * SW;

            if (SELF) {
                #pragma unroll 4
                for (int c = 0; c < 64; c += 2) {
                    ull bv[6];
                    #pragma unroll
                    for (int s = 0; s < 6; s++) bv[s] = ld2(bp + s * 16 * SW + c);
                    #pragma unroll
                    for (int i = 0; i < 4; i++) {
                        ull av = ld2(aq[i] + c);
                        #pragma unroll
                        for (int s = 0; s < 6; s++)
                            acc[i][s] = ffma2(av, bv[s], acc[i][s]);
                    }
                }
            } else if (eh == 0) {
                // s<4 -> Q section (e<64, uses Q rows); s=4,5 -> K (KV rows)
                #pragma unroll 4
                for (int c = 0; c < 64; c += 2) {
                    ull bv[6];
                    #pragma unroll
                    for (int s = 0; s < 6; s++) bv[s] = ld2(bp + s * 16 * SW + c);
                    #pragma unroll
                    for (int i = 0; i < 4; i++) {
                        ull avq = ld2(aq[i] + c);
                        ull avk = ld2(ak[i] + c);
                        #pragma unroll
                        for (int s = 0; s < 4; s++)
                            acc[i][s] = ffma2(avq, bv[s], acc[i][s]);
                        acc[i][4] = ffma2(avk, bv[4], acc[i][4]);
                        acc[i][5] = ffma2(avk, bv[5], acc[i][5]);
                    }
                }
            } else {
                // e >= 96: all K/V sections, KV rows only
                #pragma unroll 4
                for (int c = 0; c < 64; c += 2) {
                    ull bv[6];
                    #pragma unroll
                    for (int s = 0; s < 6; s++) bv[s] = ld2(bp + s * 16 * SW + c);
                    #pragma unroll
                    for (int i = 0; i < 4; i++) {
                        ull avk = ld2(ak[i] + c);
                        #pragma unroll
                        for (int s = 0; s < 6; s++)
                            acc[i][s] = ffma2(avk, bv[s], acc[i][s]);
                    }
                }
            }

            #pragma unroll
            for (int i = 0; i < 4; i++) {
                int trw = (tr0 + i) * SW;
                #pragma unroll
                for (int s = 0; s < 6; s++) {
                    float2 p = upk(acc[i][s]);
                    float v = p.x + p.y;
                    int e = kl + 16 * s + 96 * eh;
                    if (e < 64)       sq[trw + e] = v;
                    else if (e < 128) sk[trw + e - 64] = v;
                    else              sv[trw + e - 128] = v;
                }
            }
        }
        __syncthreads();

        // ---- attention: warp w handles batch row w -----------------------
        {
            const float* sq_r = sq + w * 4 * SW;
            const float* sk_r = sk + w * 4 * SW;
            const float* sv_r = sv + w * 4 * SW;
            float* satt_r = satt + w * 64;

            float a01[2];
            #pragma unroll
            for (int z = 0; z < 2; z++) {
                int m = lane + 32 * z;
                int h = m >> 4, i = (m >> 2) & 3, j = m & 3;
                float dot = 0.f;
                #pragma unroll
                for (int dd2 = 0; dd2 < 16; dd2++)
                    dot += sq_r[i * SW + h * 16 + dd2] * sk_r[j * SW + h * 16 + dd2];
                a01[z] = dot * 0.25f;
            }
            float m0 = a01[0], m1 = a01[1];
            m0 = fmaxf(m0, __shfl_xor_sync(0xffffffffu, m0, 1));
            m0 = fmaxf(m0, __shfl_xor_sync(0xffffffffu, m0, 2));
            m1 = fmaxf(m1, __shfl_xor_sync(0xffffffffu, m1, 1));
            m1 = fmaxf(m1, __shfl_xor_sync(0xffffffffu, m1, 2));
            float e0 = __expf(a01[0] - m0), e1 = __expf(a01[1] - m1);
            float s0 = e0, s1 = e1;
            s0 += __shfl_xor_sync(0xffffffffu, s0, 1);
            s0 += __shfl_xor_sync(0xffffffffu, s0, 2);
            s1 += __shfl_xor_sync(0xffffffffu, s1, 1);
            s1 += __shfl_xor_sync(0xffffffffu, s1, 2);
            satt_r[lane]      = __fdividef(e0, s0);
            satt_r[lane + 32] = __fdividef(e1, s1);
            __syncwarp();

            float os0 = 0.f, os1 = 0.f;
            int h0 = lane >> 4, h1 = h0 + 2;
            #pragma unroll
            for (int j = 0; j < 4; j++) {
                float wj0 = satt_r[h0 * 16 + j] + satt_r[h0 * 16 + 4 + j] +
                            satt_r[h0 * 16 + 8 + j] + satt_r[h0 * 16 + 12 + j];
                float wj1 = satt_r[h1 * 16 + j] + satt_r[h1 * 16 + 4 + j] +
                            satt_r[h1 * 16 + 8 + j] + satt_r[h1 * 16 + 12 + j];
                os0 += wj0 * sv_r[j * SW + lane];
                os1 += wj1 * sv_r[j * SW + lane + 32];
            }
            sos[w * SW + lane]      = os0;
            sos[w * SW + lane + 32] = os1;
            __syncwarp();
        }

        // ---- pooled out-projection: warp w -> batch row w ----------------
        {
            int e0 = kl + 32 * sg;
            int e1 = e0 + 16;
            ull acc0 = pk2(4.f * sbo[e0], 0.f);
            ull acc1 = pk2(4.f * sbo[e1], 0.f);
            const float* ar = sos + w * SW;
            const float* b0 = sWo + e0 * SW;
            const float* b1 = sWo + e1 * SW;
            #pragma unroll 4
            for (int c = 0; c < 64; c += 2) {
                ull av = ld2(ar + c);
                acc0 = ffma2(av, ld2(b0 + c), acc0);
                acc1 = ffma2(av, ld2(b1 + c), acc1);
            }
            float2 p0 = upk(acc0), p1 = upk(acc1);
            float v0 = (p0.x + p0.y) * 0.125f;
            float v1 = (p1.x + p1.y) * 0.125f;
            float* pp = pool + (r0 + w) * 64;
            if (ACCUM) { pp[e0] += v0; pp[e1] += v1; }
            else       { pp[e0] = v0;  pp[e1] = v1; }
        }
    }
}

// ---------------- final ----------------------------------------------------
__global__ __launch_bounds__(256)
void final_kernel(const float* __restrict__ Wf, const float* __restrict__ bf,
                  float* __restrict__ out)
{
    int b = blockIdx.x * blockDim.x + threadIdx.x;
    if (b >= BB) return;
    const float4* pa = (const float4*)(g_poolA + b * 64);
    const float4* pb = (const float4*)(g_poolB + b * 64);
    float s = bf[0];
    #pragma unroll
    for (int i = 0; i < 16; i++) {
        float4 v = pa[i];
        float4 wv = *(const float4*)(Wf + 4 * i);
        s += v.x * wv.x + v.y * wv.y + v.z * wv.z + v.w * wv.w;
    }
    #pragma unroll
    for (int i = 0; i < 16; i++) {
        float4 v = pb[i];
        float4 wv = *(const float4*)(Wf + 64 + 4 * i);
        s += v.x * wv.x + v.y * wv.y + v.z * wv.z + v.w * wv.w;
    }
    out[b] = (s > 0.f) ? s : 0.01f * s;
}

// ---------------- launch ----------------------------------------------------
static const int A_SMEM = TOK_SMEM_F * 4;   // 168448 B
static const int M_SMEM = MHA_SMEM_F * 4;   // 115008 B

extern "C" void kernel_launch(void* const* d_in, const int* in_sizes, int n_in,
                              void* d_out, int out_size)
{
    (void)in_sizes; (void)n_in; (void)out_size;
    const float* x  = (const float*)d_in[0];
    const float* w1 = (const float*)d_in[1];
    const float* b1 = (const float*)d_in[2];
    const float* w2 = (const float*)d_in[3];
    const float* b2 = (const float*)d_in[4];
    const float* w3 = (const float*)d_in[5];
    const float* b3 = (const float*)d_in[6];
    const float* Win_sa = (const float*)d_in[7];
    const float* bin_sa = (const float*)d_in[8];
    const float* Wo_sa  = (const float*)d_in[9];
    const float* bo_sa  = (const float*)d_in[10];
    const float* Win_sb = (const float*)d_in[11];
    const float* bin_sb = (const float*)d_in[12];
    const float* Wo_sb  = (const float*)d_in[13];
    const float* bo_sb  = (const float*)d_in[14];
    const float* Win_ca = (const float*)d_in[15];
    const float* bin_ca = (const float*)d_in[16];
    const float* Wo_ca  = (const float*)d_in[17];
    const float* bo_ca  = (const float*)d_in[18];
    const float* Win_cb = (const float*)d_in[19];
    const float* bin_cb = (const float*)d_in[20];
    const float* Wo_cb  = (const float*)d_in[21];
    const float* bo_cb  = (const float*)d_in[22];
    const float* Wf = (const float*)d_in[23];
    const float* bf = (const float*)d_in[24];
    float* out = (float*)d_out;

    cudaFuncSetAttribute(tok_kernel, cudaFuncAttributeMaxDynamicSharedMemorySize, A_SMEM);
    cudaFuncSetAttribute(mha_kernel<0, 0, false, false>, cudaFuncAttributeMaxDynamicSharedMemorySize, M_SMEM);
    cudaFuncSetAttribute(mha_kernel<4, 4, false, true>,  cudaFuncAttributeMaxDynamicSharedMemorySize, M_SMEM);
    cudaFuncSetAttribute(mha_kernel<0, 4, true,  false>, cudaFuncAttributeMaxDynamicSharedMemorySize, M_SMEM);
    cudaFuncSetAttribute(mha_kernel<4, 0, true,  true>,  cudaFuncAttributeMaxDynamicSharedMemorySize, M_SMEM);

    tok_kernel<<<dim3(37, 8), 512, A_SMEM>>>(x, w1, b1, w2, b2, w3, b3);

    mha_kernel<0, 0, false, false><<<296, 256, M_SMEM>>>(Win_sa, bin_sa, Wo_sa, bo_sa);
    mha_kernel<4, 4, false, true ><<<296, 256, M_SMEM>>>(Win_sb, bin_sb, Wo_sb, bo_sb);
    mha_kernel<0, 4, true,  false><<<296, 256, M_SMEM>>>(Win_ca, bin_ca, Wo_ca, bo_ca);
    mha_kernel<4, 0, true,  true ><<<296, 256, M_SMEM>>>(Win_cb, bin_cb, Wo_cb, bo_cb);

    final_kernel<<<BB / 256, 256>>>(Wf, bf, out);
}

// round 7
// speedup vs baseline: 1.3416x; 1.0410x over previous
#include <cuda_runtime.h>

#define BB 65536
#define DD 8
#define HH 128
#define EE 64

typedef unsigned long long ull;

__device__ __forceinline__ ull ffma2(ull a, ull b, ull c) {
    ull d;
    asm("fma.rn.f32x2 %0,%1,%2,%3;" : "=l"(d) : "l"(a), "l"(b), "l"(c));
    return d;
}
__device__ __forceinline__ ull add2(ull a, ull b) {
    ull d;
    asm("add.rn.f32x2 %0,%1,%2;" : "=l"(d) : "l"(a), "l"(b));
    return d;
}
__device__ __forceinline__ ull pk2(float lo, float hi) {
    ull r;
    asm("mov.b64 %0,{%1,%2};" : "=l"(r) : "f"(lo), "f"(hi));
    return r;
}
__device__ __forceinline__ float2 upk(ull v) {
    float2 r;
    asm("mov.b64 {%0,%1},%2;" : "=f"(r.x), "=f"(r.y) : "l"(v));
    return r;
}
__device__ __forceinline__ ull ld2(const float* p) {
    return *(const ull*)p;
}

// ---------------- scratch ---------------------------------------------------
__device__ float g_tok[BB * DD * EE];   // [b][token d][o]
__device__ float g_poolA[BB * EE];
__device__ float g_poolB[BB * EE];

// ============================================================================
// Kernel A: tokens = W3 sin(W2 sin(x*w1+b1)+b2)+b3   (unchanged from R6)
// ============================================================================
#define ST 130
#define TOK_SMEM_F (128*ST + 64*ST + 64*ST + 64*ST + 128*3 + 64 + 64)  // 42112

__global__ __launch_bounds__(512, 1)
void tok_kernel(const float* __restrict__ x,
                const float* __restrict__ w1, const float* __restrict__ b1,
                const float* __restrict__ w2, const float* __restrict__ b2,
                const float* __restrict__ w3, const float* __restrict__ b3)
{
    extern __shared__ float sm[];
    float* sW2  = sm;                    // [k][h] native, stride 130
    float* sW3  = sW2 + 128 * ST;        // [o][h]
    float* sh1  = sW3 + 64 * ST;         // [r][h]
    float* sh2  = sh1 + 64 * ST;         // [r][k]
    float* sw1c = sh2 + 64 * ST;         // 128
    float* sb1c = sw1c + 128;
    float* sb2c = sb1c + 128;
    float* sb3c = sb2c + 128;            // 64
    float* sx   = sb3c + 64;             // 64

    const int d    = blockIdx.y;
    const int tid  = threadIdx.x;
    const int w    = tid >> 5, lane = tid & 31;
    const int kl   = lane & 15, sg = lane >> 4;
    const int eh   = w & 1;
    const int rgw  = w >> 1;
    const int tr0  = rgw * 8 + sg * 4;

    for (int i = tid; i < HH * HH; i += 512) {
        int k = i >> 7, h = i & 127;
        sW2[k * ST + h] = w2[d * HH * HH + i];
    }
    for (int i = tid; i < EE * HH; i += 512) {
        int o = i >> 7, h = i & 127;
        sW3[o * ST + h] = w3[d * EE * HH + i];
    }
    if (tid < 128) {
        sw1c[tid] = w1[d * HH + tid];
        sb1c[tid] = b1[d * HH + tid];
        sb2c[tid] = b2[d * HH + tid];
    }
    if (tid < 64) sb3c[tid] = b3[d * EE + tid];

    for (int t = blockIdx.x; t < BB / 64; t += gridDim.x) {
        const int r0 = t * 64;
        __syncthreads();
        if (tid < 64) sx[tid] = x[(r0 + tid) * DD + d];
        __syncthreads();

        for (int i = tid; i < 64 * HH; i += 512) {
            int r = i >> 7, h = i & 127;
            sh1[r * ST + h] = __sinf(sx[r] * sw1c[h] + sb1c[h]);
        }
        __syncthreads();

        // GEMM1
        {
            ull acc[4][4];
            #pragma unroll
            for (int i = 0; i < 4; i++)
                #pragma unroll
                for (int s = 0; s < 4; s++) acc[i][s] = 0ull;

            const float* bp = sW2 + (kl + 64 * eh) * ST;
            const float* a0 = sh1 + tr0 * ST;
            #pragma unroll 4
            for (int h = 0; h < HH; h += 2) {
                ull bv[4];
                #pragma unroll
                for (int s = 0; s < 4; s++) bv[s] = ld2(bp + s * 16 * ST + h);
                #pragma unroll
                for (int i = 0; i < 4; i++) {
                    ull av = ld2(a0 + i * ST + h);
                    #pragma unroll
                    for (int s = 0; s < 4; s++)
                        acc[i][s] = ffma2(av, bv[s], acc[i][s]);
                }
            }
            #pragma unroll
            for (int i = 0; i < 4; i++)
                #pragma unroll
                for (int s = 0; s < 4; s++) {
                    float2 p = upk(acc[i][s]);
                    int k = kl + 16 * s + 64 * eh;
                    sh2[(tr0 + i) * ST + k] = __sinf(p.x + p.y + sb2c[k]);
                }
        }
        __syncthreads();

        // GEMM2
        {
            ull acc[4][2];
            #pragma unroll
            for (int i = 0; i < 4; i++)
                #pragma unroll
                for (int s = 0; s < 2; s++)
                    acc[i][s] = pk2(sb3c[kl + 16 * s + 32 * eh], 0.f);

            const float* bp = sW3 + (kl + 32 * eh) * ST;
            const float* a0 = sh2 + tr0 * ST;
            #pragma unroll 4
            for (int h = 0; h < HH; h += 2) {
                ull bv[2];
                #pragma unroll
                for (int s = 0; s < 2; s++) bv[s] = ld2(bp + s * 16 * ST + h);
                #pragma unroll
                for (int i = 0; i < 4; i++) {
                    ull av = ld2(a0 + i * ST + h);
                    #pragma unroll
                    for (int s = 0; s < 2; s++)
                        acc[i][s] = ffma2(av, bv[s], acc[i][s]);
                }
            }
            #pragma unroll
            for (int i = 0; i < 4; i++)
                #pragma unroll
                for (int s = 0; s < 2; s++) {
                    float2 p = upk(acc[i][s]);
                    int e = kl + 16 * s + 32 * eh;
                    g_tok[((r0 + tr0 + i) * DD + d) * EE + e] = p.x + p.y;
                }
        }
    }
}

// ============================================================================
// MHA: 256 threads, tile 8 batch rows, 2 blocks/SM.
// float4 staging (stok stride 68), f32x2 attention, reg-blocked projections.
// ============================================================================
#define SW 66          // stride for weights + q/k/v (ld2-conflict-free)
#define SWT 68         // stride for stok (float4-aligned; a-loads are broadcasts)
// layout: sWin 192*66 | sWo 64*66 | sbin 192 | sbo 64 | sq/sk/sv 3*8*4*66
//         | satt 8*64 | sos 8*64 | stok (last, size differs self/cross)
#define MHA_PREFIX_F (192*SW + 64*SW + 192 + 64 + 3*8*4*SW + 8*64 + 8*64)  // 24512
#define MHA_SELF_F  (MHA_PREFIX_F + 8*4*SWT)   // 26688
#define MHA_CROSS_F (MHA_PREFIX_F + 8*8*SWT)   // 28864

template<int QOFF, int KVOFF, bool ACCUM, bool POOLB>
__global__ __launch_bounds__(256, 2)
void mha_kernel(const float* __restrict__ Win, const float* __restrict__ bin,
                const float* __restrict__ Wo,  const float* __restrict__ bo)
{
    extern __shared__ float sm[];
    float* sWin = sm;                    // [e][c] stride 66 (192 rows)
    float* sWo  = sWin + 192 * SW;       // [e][c]
    float* sbin = sWo + 64 * SW;         // 192
    float* sbo  = sbin + 192;            // 64
    float* sq   = sbo + 64;              // [tr][66], tr = br*4+tk (32 rows)
    float* sk   = sq + 8 * 4 * SW;
    float* sv   = sk + 8 * 4 * SW;
    float* satt = sv + 8 * 4 * SW;       // [br][64]
    float* sos  = satt + 512;            // [br][64]
    float* stok = sos + 512;             // [trow][68]

    const int tid  = threadIdx.x;
    const int w    = tid >> 5, lane = tid & 31;
    const int kl   = lane & 15, sg = lane >> 4;
    const int eh   = w & 1;
    const int rgw  = w >> 1;
    const int tr0  = rgw * 8 + sg * 4;

    constexpr bool SELF = (QOFF == KVOFF);

    for (int i = tid; i < 192 * 64; i += 256) {
        int e = i >> 6, c = i & 63;
        sWin[e * SW + c] = Win[i];
    }
    for (int i = tid; i < 64 * 64; i += 256) {
        int e = i >> 6, c = i & 63;
        sWo[e * SW + c] = Wo[i];
    }
    if (tid < 192) sbin[tid] = bin[tid];
    if (tid < 64)  sbo[tid]  = bo[tid];

    float* pool = POOLB ? g_poolB : g_poolA;

    for (int t = blockIdx.x; t < BB / 8; t += gridDim.x) {
        const int r0 = t * 8;
        __syncthreads();             // prev tile fully consumed

        // ---- float4 staging into stride-68 stok --------------------------
        if (SELF) {
            #pragma unroll
            for (int i2 = 0; i2 < 2; i2++) {
                int i = tid + 256 * i2;          // 0..511 float4s
                int trow = i >> 4, c4 = i & 15;  // trow = br*4+tk
                int br = trow >> 2, tk = trow & 3;
                float4 v = *(const float4*)(g_tok + (r0 + br) * 512 +
                                            (QOFF + tk) * 64 + c4 * 4);
                *(float4*)(stok + trow * SWT + c4 * 4) = v;
            }
        } else {
            const float4* src = (const float4*)(g_tok + r0 * 512);
            #pragma unroll
            for (int i2 = 0; i2 < 4; i2++) {
                int i = tid + 256 * i2;          // 0..1023 float4s (linear src)
                int trow = i >> 4, c4 = i & 15;  // trow = br*8+tk
                float4 v = src[i];
                *(float4*)(stok + trow * SWT + c4 * 4) = v;
            }
        }
        __syncthreads();

        // ---- projections: thread = 4 token-rows x 6 outputs --------------
        {
            ull acc[4][6];
            #pragma unroll
            for (int i = 0; i < 4; i++)
                #pragma unroll
                for (int s = 0; s < 6; s++)
                    acc[i][s] = pk2(sbin[kl + 16 * s + 96 * eh], 0.f);

            const float* aq[4];
            const float* ak[4];
            #pragma unroll
            for (int i = 0; i < 4; i++) {
                int tr = tr0 + i, br = tr >> 2, tk = tr & 3;
                if (SELF) {
                    aq[i] = stok + tr * SWT;
                    ak[i] = aq[i];
                } else {
                    aq[i] = stok + (br * 8 + QOFF + tk) * SWT;
                    ak[i] = stok + (br * 8 + KVOFF + tk) * SWT;
                }
            }
            const float* bp = sWin + (kl + 96 * eh) * SW;

            if (SELF) {
                #pragma unroll 4
                for (int c = 0; c < 64; c += 2) {
                    ull bv[6];
                    #pragma unroll
                    for (int s = 0; s < 6; s++) bv[s] = ld2(bp + s * 16 * SW + c);
                    #pragma unroll
                    for (int i = 0; i < 4; i++) {
                        ull av = ld2(aq[i] + c);
                        #pragma unroll
                        for (int s = 0; s < 6; s++)
                            acc[i][s] = ffma2(av, bv[s], acc[i][s]);
                    }
                }
            } else if (eh == 0) {
                #pragma unroll 4
                for (int c = 0; c < 64; c += 2) {
                    ull bv[6];
                    #pragma unroll
                    for (int s = 0; s < 6; s++) bv[s] = ld2(bp + s * 16 * SW + c);
                    #pragma unroll
                    for (int i = 0; i < 4; i++) {
                        ull avq = ld2(aq[i] + c);
                        ull avk = ld2(ak[i] + c);
                        #pragma unroll
                        for (int s = 0; s < 4; s++)
                            acc[i][s] = ffma2(avq, bv[s], acc[i][s]);
                        acc[i][4] = ffma2(avk, bv[4], acc[i][4]);
                        acc[i][5] = ffma2(avk, bv[5], acc[i][5]);
                    }
                }
            } else {
                #pragma unroll 4
                for (int c = 0; c < 64; c += 2) {
                    ull bv[6];
                    #pragma unroll
                    for (int s = 0; s < 6; s++) bv[s] = ld2(bp + s * 16 * SW + c);
                    #pragma unroll
                    for (int i = 0; i < 4; i++) {
                        ull avk = ld2(ak[i] + c);
                        #pragma unroll
                        for (int s = 0; s < 6; s++)
                            acc[i][s] = ffma2(avk, bv[s], acc[i][s]);
                    }
                }
            }

            #pragma unroll
            for (int i = 0; i < 4; i++) {
                int trw = (tr0 + i) * SW;
                #pragma unroll
                for (int s = 0; s < 6; s++) {
                    float2 p = upk(acc[i][s]);
                    float v = p.x + p.y;
                    int e = kl + 16 * s + 96 * eh;
                    if (e < 64)       sq[trw + e] = v;
                    else if (e < 128) sk[trw + e - 64] = v;
                    else              sv[trw + e - 128] = v;
                }
            }
        }
        __syncthreads();

        // ---- attention (f32x2): warp w handles batch row w ---------------
        {
            const float* sq_r = sq + w * 4 * SW;
            const float* sk_r = sk + w * 4 * SW;
            const float* sv_r = sv + w * 4 * SW;
            float* satt_r = satt + w * 64;

            float a01[2];
            #pragma unroll
            for (int z = 0; z < 2; z++) {
                int m = lane + 32 * z;
                int h = m >> 4, i = (m >> 2) & 3, j = m & 3;
                const float* qb = sq_r + i * SW + h * 16;
                const float* kb = sk_r + j * SW + h * 16;
                ull acc = 0ull;
                #pragma unroll
                for (int dd2 = 0; dd2 < 16; dd2 += 2)
                    acc = ffma2(ld2(qb + dd2), ld2(kb + dd2), acc);
                float2 p = upk(acc);
                a01[z] = (p.x + p.y) * 0.25f;
            }
            float m0 = a01[0], m1 = a01[1];
            m0 = fmaxf(m0, __shfl_xor_sync(0xffffffffu, m0, 1));
            m0 = fmaxf(m0, __shfl_xor_sync(0xffffffffu, m0, 2));
            m1 = fmaxf(m1, __shfl_xor_sync(0xffffffffu, m1, 1));
            m1 = fmaxf(m1, __shfl_xor_sync(0xffffffffu, m1, 2));
            float e0 = __expf(a01[0] - m0), e1 = __expf(a01[1] - m1);
            float s0 = e0, s1 = e1;
            s0 += __shfl_xor_sync(0xffffffffu, s0, 1);
            s0 += __shfl_xor_sync(0xffffffffu, s0, 2);
            s1 += __shfl_xor_sync(0xffffffffu, s1, 1);
            s1 += __shfl_xor_sync(0xffffffffu, s1, 2);
            satt_r[lane]      = __fdividef(e0, s0);
            satt_r[lane + 32] = __fdividef(e1, s1);
            __syncwarp();

            float os0 = 0.f, os1 = 0.f;
            int h0 = lane >> 4, h1 = h0 + 2;
            #pragma unroll
            for (int j2 = 0; j2 < 4; j2 += 2) {
                ull w0 = add2(add2(ld2(satt_r + h0 * 16 + j2),
                                   ld2(satt_r + h0 * 16 + 4 + j2)),
                              add2(ld2(satt_r + h0 * 16 + 8 + j2),
                                   ld2(satt_r + h0 * 16 + 12 + j2)));
                ull w1 = add2(add2(ld2(satt_r + h1 * 16 + j2),
                                   ld2(satt_r + h1 * 16 + 4 + j2)),
                              add2(ld2(satt_r + h1 * 16 + 8 + j2),
                                   ld2(satt_r + h1 * 16 + 12 + j2)));
                float2 q0 = upk(w0), q1 = upk(w1);
                os0 += q0.x * sv_r[j2 * SW + lane] +
                       q0.y * sv_r[(j2 + 1) * SW + lane];
                os1 += q1.x * sv_r[j2 * SW + lane + 32] +
                       q1.y * sv_r[(j2 + 1) * SW + lane + 32];
            }
            sos[w * 64 + lane]      = os0;
            sos[w * 64 + lane + 32] = os1;
            __syncwarp();
        }

        // ---- pooled out-projection: warp w -> batch row w ----------------
        {
            int e0 = kl + 32 * sg;
            int e1 = e0 + 16;
            ull acc0 = pk2(4.f * sbo[e0], 0.f);
            ull acc1 = pk2(4.f * sbo[e1], 0.f);
            const float* ar = sos + w * 64;
            const float* b0 = sWo + e0 * SW;
            const float* b1 = sWo + e1 * SW;
            #pragma unroll 4
            for (int c = 0; c < 64; c += 2) {
                ull av = ld2(ar + c);
                acc0 = ffma2(av, ld2(b0 + c), acc0);
                acc1 = ffma2(av, ld2(b1 + c), acc1);
            }
            float2 p0 = upk(acc0), p1 = upk(acc1);
            float v0 = (p0.x + p0.y) * 0.125f;
            float v1 = (p1.x + p1.y) * 0.125f;
            float* pp = pool + (r0 + w) * 64;
            if (ACCUM) { pp[e0] += v0; pp[e1] += v1; }
            else       { pp[e0] = v0;  pp[e1] = v1; }
        }
    }
}

// ---------------- final ----------------------------------------------------
__global__ __launch_bounds__(256)
void final_kernel(const float* __restrict__ Wf, const float* __restrict__ bf,
                  float* __restrict__ out)
{
    int b = blockIdx.x * blockDim.x + threadIdx.x;
    if (b >= BB) return;
    const float4* pa = (const float4*)(g_poolA + b * 64);
    const float4* pb = (const float4*)(g_poolB + b * 64);
    float s = bf[0];
    #pragma unroll
    for (int i = 0; i < 16; i++) {
        float4 v = pa[i];
        float4 wv = *(const float4*)(Wf + 4 * i);
        s += v.x * wv.x + v.y * wv.y + v.z * wv.z + v.w * wv.w;
    }
    #pragma unroll
    for (int i = 0; i < 16; i++) {
        float4 v = pb[i];
        float4 wv = *(const float4*)(Wf + 64 + 4 * i);
        s += v.x * wv.x + v.y * wv.y + v.z * wv.z + v.w * wv.w;
    }
    out[b] = (s > 0.f) ? s : 0.01f * s;
}

// ---------------- launch ----------------------------------------------------
static const int A_SMEM  = TOK_SMEM_F * 4;    // 168448 B
static const int M_SMEM_S = MHA_SELF_F * 4;   // 106752 B
static const int M_SMEM_C = MHA_CROSS_F * 4;  // 115456 B

extern "C" void kernel_launch(void* const* d_in, const int* in_sizes, int n_in,
                              void* d_out, int out_size)
{
    (void)in_sizes; (void)n_in; (void)out_size;
    const float* x  = (const float*)d_in[0];
    const float* w1 = (const float*)d_in[1];
    const float* b1 = (const float*)d_in[2];
    const float* w2 = (const float*)d_in[3];
    const float* b2 = (const float*)d_in[4];
    const float* w3 = (const float*)d_in[5];
    const float* b3 = (const float*)d_in[6];
    const float* Win_sa = (const float*)d_in[7];
    const float* bin_sa = (const float*)d_in[8];
    const float* Wo_sa  = (const float*)d_in[9];
    const float* bo_sa  = (const float*)d_in[10];
    const float* Win_sb = (const float*)d_in[11];
    const float* bin_sb = (const float*)d_in[12];
    const float* Wo_sb  = (const float*)d_in[13];
    const float* bo_sb  = (const float*)d_in[14];
    const float* Win_ca = (const float*)d_in[15];
    const float* bin_ca = (const float*)d_in[16];
    const float* Wo_ca  = (const float*)d_in[17];
    const float* bo_ca  = (const float*)d_in[18];
    const float* Win_cb = (const float*)d_in[19];
    const float* bin_cb = (const float*)d_in[20];
    const float* Wo_cb  = (const float*)d_in[21];
    const float* bo_cb  = (const float*)d_in[22];
    const float* Wf = (const float*)d_in[23];
    const float* bf = (const float*)d_in[24];
    float* out = (float*)d_out;

    cudaFuncSetAttribute(tok_kernel, cudaFuncAttributeMaxDynamicSharedMemorySize, A_SMEM);
    cudaFuncSetAttribute(mha_kernel<0, 0, false, false>, cudaFuncAttributeMaxDynamicSharedMemorySize, M_SMEM_S);
    cudaFuncSetAttribute(mha_kernel<4, 4, false, true>,  cudaFuncAttributeMaxDynamicSharedMemorySize, M_SMEM_S);
    cudaFuncSetAttribute(mha_kernel<0, 4, true,  false>, cudaFuncAttributeMaxDynamicSharedMemorySize, M_SMEM_C);
    cudaFuncSetAttribute(mha_kernel<4, 0, true,  true>,  cudaFuncAttributeMaxDynamicSharedMemorySize, M_SMEM_C);

    tok_kernel<<<dim3(37, 8), 512, A_SMEM>>>(x, w1, b1, w2, b2, w3, b3);

    mha_kernel<0, 0, false, false><<<296, 256, M_SMEM_S>>>(Win_sa, bin_sa, Wo_sa, bo_sa);
    mha_kernel<4, 4, false, true ><<<296, 256, M_SMEM_S>>>(Win_sb, bin_sb, Wo_sb, bo_sb);
    mha_kernel<0, 4, true,  false><<<296, 256, M_SMEM_C>>>(Win_ca, bin_ca, Wo_ca, bo_ca);
    mha_kernel<4, 0, true,  true ><<<296, 256, M_SMEM_C>>>(Win_cb, bin_cb, Wo_cb, bo_cb);

    final_kernel<<<BB / 256, 256>>>(Wf, bf, out);
}

// round 8
// speedup vs baseline: 1.5701x; 1.1703x over previous
#include <cuda_runtime.h>

#define BB 65536
#define DD 8
#define HH 128
#define EE 64

typedef unsigned long long ull;

__device__ __forceinline__ ull ffma2(ull a, ull b, ull c) {
    ull d;
    asm("fma.rn.f32x2 %0,%1,%2,%3;" : "=l"(d) : "l"(a), "l"(b), "l"(c));
    return d;
}
__device__ __forceinline__ ull pk2(float lo, float hi) {
    ull r;
    asm("mov.b64 %0,{%1,%2};" : "=l"(r) : "f"(lo), "f"(hi));
    return r;
}
__device__ __forceinline__ float2 upk(ull v) {
    float2 r;
    asm("mov.b64 {%0,%1},%2;" : "=f"(r.x), "=f"(r.y) : "l"(v));
    return r;
}
__device__ __forceinline__ ull ld2(const float* p) {
    return *(const ull*)p;
}

// FFMA-only sin: reduce to [-pi,pi], degree-11 odd minimax (XMScalarSin).
__device__ __forceinline__ float fast_sin(float x) {
    float k = rintf(x * 0.15915494309f);           // x / (2*pi)
    float r = fmaf(k, -6.2831855f, x);             // float(2*pi) = 6.28318548...
    r = fmaf(k, 1.7484555e-7f, r);                 // float(2*pi) - 2*pi correction
    float r2 = r * r;
    float p = -2.3889859e-8f;
    p = fmaf(p, r2, 2.7525562e-6f);
    p = fmaf(p, r2, -1.9840874e-4f);
    p = fmaf(p, r2, 8.3333310e-3f);
    p = fmaf(p, r2, -1.6666667e-1f);
    p = fmaf(p, r2, 1.0f);
    return r * p;
}

// ---------------- scratch ---------------------------------------------------
__device__ float g_tok[BB * DD * EE];   // [b][token d][o]
__device__ float g_S[BB];               // folded scalar accumulator

// ============================================================================
// Kernel A: tokens = W3 sin(W2 sin(x*w1+b1)+b2)+b3
// ============================================================================
#define ST 130
#define TOK_SMEM_F (128*ST + 64*ST + 64*ST + 64*ST + 128*3 + 64 + 64)  // 42112

__global__ __launch_bounds__(512, 1)
void tok_kernel(const float* __restrict__ x,
                const float* __restrict__ w1, const float* __restrict__ b1,
                const float* __restrict__ w2, const float* __restrict__ b2,
                const float* __restrict__ w3, const float* __restrict__ b3)
{
    extern __shared__ float sm[];
    float* sW2  = sm;                    // [k][h] native, stride 130
    float* sW3  = sW2 + 128 * ST;        // [o][h]
    float* sh1  = sW3 + 64 * ST;         // [r][h]
    float* sh2  = sh1 + 64 * ST;         // [r][k]
    float* sw1c = sh2 + 64 * ST;         // 128
    float* sb1c = sw1c + 128;
    float* sb2c = sb1c + 128;
    float* sb3c = sb2c + 128;            // 64
    float* sx   = sb3c + 64;             // 64

    const int d    = blockIdx.y;
    const int tid  = threadIdx.x;
    const int w    = tid >> 5, lane = tid & 31;
    const int kl   = lane & 15, sg = lane >> 4;
    const int eh   = w & 1;
    const int rgw  = w >> 1;
    const int tr0  = rgw * 8 + sg * 4;

    for (int i = tid; i < HH * HH; i += 512) {
        int k = i >> 7, h = i & 127;
        sW2[k * ST + h] = w2[d * HH * HH + i];
    }
    for (int i = tid; i < EE * HH; i += 512) {
        int o = i >> 7, h = i & 127;
        sW3[o * ST + h] = w3[d * EE * HH + i];
    }
    if (tid < 128) {
        sw1c[tid] = w1[d * HH + tid];
        sb1c[tid] = b1[d * HH + tid];
        sb2c[tid] = b2[d * HH + tid];
    }
    if (tid < 64) sb3c[tid] = b3[d * EE + tid];

    for (int t = blockIdx.x; t < BB / 64; t += gridDim.x) {
        const int r0 = t * 64;
        __syncthreads();
        if (tid < 64) sx[tid] = x[(r0 + tid) * DD + d];
        __syncthreads();

        for (int i = tid; i < 64 * HH; i += 512) {
            int r = i >> 7, h = i & 127;
            sh1[r * ST + h] = fast_sin(fmaf(sx[r], sw1c[h], sb1c[h]));
        }
        __syncthreads();

        // GEMM1
        {
            ull acc[4][4];
            #pragma unroll
            for (int i = 0; i < 4; i++)
                #pragma unroll
                for (int s = 0; s < 4; s++) acc[i][s] = 0ull;

            const float* bp = sW2 + (kl + 64 * eh) * ST;
            const float* a0 = sh1 + tr0 * ST;
            #pragma unroll 4
            for (int h = 0; h < HH; h += 2) {
                ull bv[4];
                #pragma unroll
                for (int s = 0; s < 4; s++) bv[s] = ld2(bp + s * 16 * ST + h);
                #pragma unroll
                for (int i = 0; i < 4; i++) {
                    ull av = ld2(a0 + i * ST + h);
                    #pragma unroll
                    for (int s = 0; s < 4; s++)
                        acc[i][s] = ffma2(av, bv[s], acc[i][s]);
                }
            }
            #pragma unroll
            for (int i = 0; i < 4; i++)
                #pragma unroll
                for (int s = 0; s < 4; s++) {
                    float2 p = upk(acc[i][s]);
                    int k = kl + 16 * s + 64 * eh;
                    sh2[(tr0 + i) * ST + k] = fast_sin(p.x + p.y + sb2c[k]);
                }
        }
        __syncthreads();

        // GEMM2
        {
            ull acc[4][2];
            #pragma unroll
            for (int i = 0; i < 4; i++)
                #pragma unroll
                for (int s = 0; s < 2; s++)
                    acc[i][s] = pk2(sb3c[kl + 16 * s + 32 * eh], 0.f);

            const float* bp = sW3 + (kl + 32 * eh) * ST;
            const float* a0 = sh2 + tr0 * ST;
            #pragma unroll 4
            for (int h = 0; h < HH; h += 2) {
                ull bv[2];
                #pragma unroll
                for (int s = 0; s < 2; s++) bv[s] = ld2(bp + s * 16 * ST + h);
                #pragma unroll
                for (int i = 0; i < 4; i++) {
                    ull av = ld2(a0 + i * ST + h);
                    #pragma unroll
                    for (int s = 0; s < 2; s++)
                        acc[i][s] = ffma2(av, bv[s], acc[i][s]);
                }
            }
            #pragma unroll
            for (int i = 0; i < 4; i++)
                #pragma unroll
                for (int s = 0; s < 2; s++) {
                    float2 p = upk(acc[i][s]);
                    int e = kl + 16 * s + 32 * eh;
                    g_tok[((r0 + tr0 + i) * DD + d) * EE + e] = p.x + p.y;
                }
        }
    }
}

// ============================================================================
// MHA (folded): per row computes S += Wf_slice . (0.5*mean_i out_proj(attn)_i)
// Only Q,K projections remain as GEMMs; V/out-proj folded into u, m_h.
// ============================================================================
#define SW 66          // stride for Wqk + q/k
#define SWT 68         // stride for stok (float4-aligned)
#define SMH 66         // stride for m_h rows (bank-spread for ld2)
// layout: sWqk 128*66 | sbqk 128 | sm 4*66 | su 64 | scb 8 | sq 32*66 | sk 32*66
//         | satt 8*64 | stok (self 32*68 / cross 64*68)
#define MHA_PREFIX_F (128*SW + 128 + 4*SMH + 64 + 8 + 2*32*SW + 8*64)
#define MHA_SELF_F  (MHA_PREFIX_F + 32*SWT)
#define MHA_CROSS_F (MHA_PREFIX_F + 64*SWT)

template<int QOFF, int KVOFF, bool ACCUM, bool POOLB>
__global__ __launch_bounds__(256, 2)
void mha_kernel(const float* __restrict__ Win, const float* __restrict__ bin,
                const float* __restrict__ Wo,  const float* __restrict__ Wf)
{
    extern __shared__ float sm_[];
    float* sWqk = sm_;                   // [e][c] e<64: Wq rows, e>=64: Wk rows
    float* sbqk = sWqk + 128 * SW;       // 128
    float* smh  = sbqk + 128;            // [h][64] stride 66
    float* su   = smh + 4 * SMH;         // 64
    float* scb  = su + 64;               // [0] = 0.5 * sum_h u.bv_h
    float* sq   = scb + 8;               // [tr][66] (32 rows)
    float* sk   = sq + 32 * SW;
    float* satt = sk + 32 * SW;          // [br][64]
    float* stok = satt + 512;            // [trow][68]

    const int tid  = threadIdx.x;
    const int w    = tid >> 5, lane = tid & 31;
    const int kl   = lane & 15, sg = lane >> 4;
    const int eh   = w & 1;
    const int rgw  = w >> 1;
    const int tr0  = rgw * 8 + sg * 4;

    constexpr bool SELF = (QOFF == KVOFF);
    constexpr int FOFF = POOLB ? 64 : 0;

    // ---- stage Wq/Wk + biases ----
    for (int i = tid; i < 128 * 64; i += 256) {
        int e = i >> 6, c = i & 63;
        sWqk[e * SW + c] = Win[i];
    }
    if (tid < 128) sbqk[tid] = bin[tid];

    // ---- u_c = sum_e Wf[FOFF+e] * Wo[e][c] ----
    if (tid < 64) {
        float s = 0.f;
        for (int e = 0; e < 64; e++) s = fmaf(Wf[FOFF + e], Wo[e * 64 + tid], s);
        su[tid] = s;
    }
    __syncthreads();

    // ---- m_h[d] = sum_{c in head h} u_c * Wv[c][d];  Wv row c = Win[128+c] ----
    {
        int h = tid >> 6, dd2 = tid & 63;
        float s = 0.f;
        #pragma unroll
        for (int cc = 0; cc < 16; cc++)
            s = fmaf(su[h * 16 + cc], Win[(128 + h * 16 + cc) * 64 + dd2], s);
        smh[h * SMH + dd2] = s;
    }
    if (tid == 0) {
        float s = 0.f;
        for (int c = 0; c < 64; c++) s = fmaf(su[c], bin[128 + c], s);
        scb[0] = 0.5f * s;
    }

    for (int t = blockIdx.x; t < BB / 8; t += gridDim.x) {
        const int r0 = t * 8;
        __syncthreads();             // prev tile consumed / startup done

        // ---- float4 staging ----
        if (SELF) {
            #pragma unroll
            for (int i2 = 0; i2 < 2; i2++) {
                int i = tid + 256 * i2;          // 0..511 float4s
                int trow = i >> 4, c4 = i & 15;  // trow = br*4+tk
                int br = trow >> 2, tk = trow & 3;
                float4 v = *(const float4*)(g_tok + (r0 + br) * 512 +
                                            (QOFF + tk) * 64 + c4 * 4);
                *(float4*)(stok + trow * SWT + c4 * 4) = v;
            }
        } else {
            const float4* src = (const float4*)(g_tok + r0 * 512);
            #pragma unroll
            for (int i2 = 0; i2 < 4; i2++) {
                int i = tid + 256 * i2;          // 0..1023 float4s
                int trow = i >> 4, c4 = i & 15;  // trow = br*8+tk
                float4 v = src[i];
                *(float4*)(stok + trow * SWT + c4 * 4) = v;
            }
        }
        __syncthreads();

        // ---- Q/K projections: thread = 4 token-rows x 4 outputs ----------
        // eh=0 warps compute Q (uses q rows), eh=1 compute K (kv rows)
        {
            ull acc[4][4];
            #pragma unroll
            for (int i = 0; i < 4; i++)
                #pragma unroll
                for (int s = 0; s < 4; s++)
                    acc[i][s] = pk2(sbqk[kl + 16 * s + 64 * eh], 0.f);

            const float* ap[4];
            #pragma unroll
            for (int i = 0; i < 4; i++) {
                int tr = tr0 + i, br = tr >> 2, tk = tr & 3;
                if (SELF) ap[i] = stok + tr * SWT;
                else      ap[i] = stok + (br * 8 + (eh ? KVOFF : QOFF) + tk) * SWT;
            }
            const float* bp = sWqk + (kl + 64 * eh) * SW;

            #pragma unroll 4
            for (int c = 0; c < 64; c += 2) {
                ull bv[4];
                #pragma unroll
                for (int s = 0; s < 4; s++) bv[s] = ld2(bp + s * 16 * SW + c);
                #pragma unroll
                for (int i = 0; i < 4; i++) {
                    ull av = ld2(ap[i] + c);
                    #pragma unroll
                    for (int s = 0; s < 4; s++)
                        acc[i][s] = ffma2(av, bv[s], acc[i][s]);
                }
            }
            float* dest = eh ? sk : sq;
            #pragma unroll
            for (int i = 0; i < 4; i++) {
                int trw = (tr0 + i) * SW;
                #pragma unroll
                for (int s = 0; s < 4; s++) {
                    float2 p = upk(acc[i][s]);
                    dest[trw + kl + 16 * s] = p.x + p.y;
                }
            }
        }
        __syncthreads();

        // ---- attention + folded pooling: warp w handles batch row w ------
        {
            const float* sq_r = sq + w * 4 * SW;
            const float* sk_r = sk + w * 4 * SW;
            float* satt_r = satt + w * 64;

            float a01[2];
            #pragma unroll
            for (int z = 0; z < 2; z++) {
                int m = lane + 32 * z;
                int h = m >> 4, i = (m >> 2) & 3, j = m & 3;
                const float* qb = sq_r + i * SW + h * 16;
                const float* kb = sk_r + j * SW + h * 16;
                ull acc = 0ull;
                #pragma unroll
                for (int dd2 = 0; dd2 < 16; dd2 += 2)
                    acc = ffma2(ld2(qb + dd2), ld2(kb + dd2), acc);
                float2 p = upk(acc);
                a01[z] = (p.x + p.y) * 0.25f;
            }
            float m0 = a01[0], m1 = a01[1];
            m0 = fmaxf(m0, __shfl_xor_sync(0xffffffffu, m0, 1));
            m0 = fmaxf(m0, __shfl_xor_sync(0xffffffffu, m0, 2));
            m1 = fmaxf(m1, __shfl_xor_sync(0xffffffffu, m1, 1));
            m1 = fmaxf(m1, __shfl_xor_sync(0xffffffffu, m1, 2));
            float e0 = __expf(a01[0] - m0), e1 = __expf(a01[1] - m1);
            float s0 = e0, s1 = e1;
            s0 += __shfl_xor_sync(0xffffffffu, s0, 1);
            s0 += __shfl_xor_sync(0xffffffffu, s0, 2);
            s1 += __shfl_xor_sync(0xffffffffu, s1, 1);
            s1 += __shfl_xor_sync(0xffffffffu, s1, 2);
            satt_r[lane]      = __fdividef(e0, s0);
            satt_r[lane + 32] = __fdividef(e1, s1);
            __syncwarp();

            // lanes 0..15: pair (h = lane>>2, j = lane&3)
            float part = 0.f;
            {
                int h = lane >> 2, j = lane & 3;
                int kvrow = SELF ? (w * 4 + j) : (w * 8 + KVOFF + j);
                const float* mh = smh + h * SMH;
                const float* tj = stok + kvrow * SWT;
                ull acc = 0ull;
                #pragma unroll
                for (int c = 0; c < 64; c += 2)
                    acc = ffma2(ld2(mh + c), ld2(tj + c), acc);
                float2 p = upk(acc);
                float sjh = p.x + p.y;
                float wbar = satt_r[h * 16 + j]     + satt_r[h * 16 + 4 + j] +
                             satt_r[h * 16 + 8 + j] + satt_r[h * 16 + 12 + j];
                part = wbar * sjh;
                if (lane >= 16) part = 0.f;
            }
            part += __shfl_down_sync(0xffffffffu, part, 8);
            part += __shfl_down_sync(0xffffffffu, part, 4);
            part += __shfl_down_sync(0xffffffffu, part, 2);
            part += __shfl_down_sync(0xffffffffu, part, 1);
            if (lane == 0) {
                float S = 0.125f * part + scb[0];
                if (ACCUM) g_S[r0 + w] += S;
                else       g_S[r0 + w]  = S;
            }
        }
    }
}

// ---------------- epilogue: out = leaky(S + C) ------------------------------
__global__ __launch_bounds__(256)
void epi_kernel(const float* __restrict__ Wf, const float* __restrict__ bf,
                const float* __restrict__ bo_sa, const float* __restrict__ bo_sb,
                const float* __restrict__ bo_ca, const float* __restrict__ bo_cb,
                float* __restrict__ out)
{
    int b = blockIdx.x * blockDim.x + threadIdx.x;
    if (b >= BB) return;
    float C = bf[0];
    #pragma unroll 4
    for (int e = 0; e < 64; e++) {
        C = fmaf(0.5f * Wf[e],      bo_sa[e] + bo_ca[e], C);
        C = fmaf(0.5f * Wf[64 + e], bo_sb[e] + bo_cb[e], C);
    }
    float s = g_S[b] + C;
    out[b] = (s > 0.f) ? s : 0.01f * s;
}

// ---------------- launch ----------------------------------------------------
static const int A_SMEM   = TOK_SMEM_F * 4;
static const int M_SMEM_S = MHA_SELF_F * 4;
static const int M_SMEM_C = MHA_CROSS_F * 4;

extern "C" void kernel_launch(void* const* d_in, const int* in_sizes, int n_in,
                              void* d_out, int out_size)
{
    (void)in_sizes; (void)n_in; (void)out_size;
    const float* x  = (const float*)d_in[0];
    const float* w1 = (const float*)d_in[1];
    const float* b1 = (const float*)d_in[2];
    const float* w2 = (const float*)d_in[3];
    const float* b2 = (const float*)d_in[4];
    const float* w3 = (const float*)d_in[5];
    const float* b3 = (const float*)d_in[6];
    const float* Win_sa = (const float*)d_in[7];
    const float* bin_sa = (const float*)d_in[8];
    const float* Wo_sa  = (const float*)d_in[9];
    const float* bo_sa  = (const float*)d_in[10];
    const float* Win_sb = (const float*)d_in[11];
    const float* bin_sb = (const float*)d_in[12];
    const float* Wo_sb  = (const float*)d_in[13];
    const float* bo_sb  = (const float*)d_in[14];
    const float* Win_ca = (const float*)d_in[15];
    const float* bin_ca = (const float*)d_in[16];
    const float* Wo_ca  = (const float*)d_in[17];
    const float* bo_ca  = (const float*)d_in[18];
    const float* Win_cb = (const float*)d_in[19];
    const float* bin_cb = (const float*)d_in[20];
    const float* Wo_cb  = (const float*)d_in[21];
    const float* bo_cb  = (const float*)d_in[22];
    const float* Wf = (const float*)d_in[23];
    const float* bf = (const float*)d_in[24];
    float* out = (float*)d_out;

    cudaFuncSetAttribute(tok_kernel, cudaFuncAttributeMaxDynamicSharedMemorySize, A_SMEM);
    cudaFuncSetAttribute(mha_kernel<0, 0, false, false>, cudaFuncAttributeMaxDynamicSharedMemorySize, M_SMEM_S);
    cudaFuncSetAttribute(mha_kernel<4, 4, true,  true>,  cudaFuncAttributeMaxDynamicSharedMemorySize, M_SMEM_S);
    cudaFuncSetAttribute(mha_kernel<0, 4, true,  false>, cudaFuncAttributeMaxDynamicSharedMemorySize, M_SMEM_C);
    cudaFuncSetAttribute(mha_kernel<4, 0, true,  true>,  cudaFuncAttributeMaxDynamicSharedMemorySize, M_SMEM_C);

    tok_kernel<<<dim3(37, 8), 512, A_SMEM>>>(x, w1, b1, w2, b2, w3, b3);

    // S accumulates all four folded contributions (sa writes, rest accumulate)
    mha_kernel<0, 0, false, false><<<296, 256, M_SMEM_S>>>(Win_sa, bin_sa, Wo_sa, Wf);
    mha_kernel<4, 4, true,  true ><<<296, 256, M_SMEM_S>>>(Win_sb, bin_sb, Wo_sb, Wf);
    mha_kernel<0, 4, true,  false><<<296, 256, M_SMEM_C>>>(Win_ca, bin_ca, Wo_ca, Wf);
    mha_kernel<4, 0, true,  true ><<<296, 256, M_SMEM_C>>>(Win_cb, bin_cb, Wo_cb, Wf);

    epi_kernel<<<BB / 256, 256>>>(Wf, bf, bo_sa, bo_sb, bo_ca, bo_cb, out);
}

// round 9
// speedup vs baseline: 1.6014x; 1.0200x over previous
#include <cuda_runtime.h>

#define BB 65536
#define DD 8
#define HH 128
#define EE 64

typedef unsigned long long ull;

__device__ __forceinline__ ull ffma2(ull a, ull b, ull c) {
    ull d;
    asm("fma.rn.f32x2 %0,%1,%2,%3;" : "=l"(d) : "l"(a), "l"(b), "l"(c));
    return d;
}
__device__ __forceinline__ ull pk2(float lo, float hi) {
    ull r;
    asm("mov.b64 %0,{%1,%2};" : "=l"(r) : "f"(lo), "f"(hi));
    return r;
}
__device__ __forceinline__ float2 upk(ull v) {
    float2 r;
    asm("mov.b64 {%0,%1},%2;" : "=f"(r.x), "=f"(r.y) : "l"(v));
    return r;
}
__device__ __forceinline__ ull ld2(const float* p) {
    return *(const ull*)p;
}
__device__ __forceinline__ ulonglong2 ld4(const float* p) {
    return *(const ulonglong2*)p;
}

// FFMA-only sin: reduce to [-pi,pi], degree-11 odd minimax.
__device__ __forceinline__ float fast_sin(float x) {
    float k = rintf(x * 0.15915494309f);
    float r = fmaf(k, -6.2831855f, x);
    r = fmaf(k, 1.7484555e-7f, r);
    float r2 = r * r;
    float p = -2.3889859e-8f;
    p = fmaf(p, r2, 2.7525562e-6f);
    p = fmaf(p, r2, -1.9840874e-4f);
    p = fmaf(p, r2, 8.3333310e-3f);
    p = fmaf(p, r2, -1.6666667e-1f);
    p = fmaf(p, r2, 1.0f);
    return r * p;
}

// ---------------- scratch ---------------------------------------------------
__device__ float g_tok[BB * DD * EE];   // [b][token d][o]
__device__ float g_S[BB];               // folded scalar accumulator

// ============================================================================
// Kernel A: tokens = W3 sin(W2 sin(x*w1+b1)+b2)+b3
// LDS.128 inner loops (4 K per step), stride 132.
// ============================================================================
#define ST 132
#define TOK_SMEM_F (320*ST + 128*3 + 64 + 64)   // 42752

__global__ __launch_bounds__(512, 1)
void tok_kernel(const float* __restrict__ x,
                const float* __restrict__ w1, const float* __restrict__ b1,
                const float* __restrict__ w2, const float* __restrict__ b2,
                const float* __restrict__ w3, const float* __restrict__ b3)
{
    extern __shared__ float sm[];
    float* sW2  = sm;                    // [k][h] native, stride 132
    float* sW3  = sW2 + 128 * ST;        // [o][h]
    float* sh1  = sW3 + 64 * ST;         // [r][h]
    float* sh2  = sh1 + 64 * ST;         // [r][k]
    float* sw1c = sh2 + 64 * ST;         // 128
    float* sb1c = sw1c + 128;
    float* sb2c = sb1c + 128;
    float* sb3c = sb2c + 128;            // 64
    float* sx   = sb3c + 64;             // 64

    const int d    = blockIdx.y;
    const int tid  = threadIdx.x;
    const int w    = tid >> 5, lane = tid & 31;
    const int kl   = lane & 15, sg = lane >> 4;
    const int eh   = w & 1;
    const int rgw  = w >> 1;
    const int tr0  = rgw * 8 + sg * 4;

    for (int i = tid; i < HH * HH; i += 512) {
        int k = i >> 7, h = i & 127;
        sW2[k * ST + h] = w2[d * HH * HH + i];
    }
    for (int i = tid; i < EE * HH; i += 512) {
        int o = i >> 7, h = i & 127;
        sW3[o * ST + h] = w3[d * EE * HH + i];
    }
    if (tid < 128) {
        sw1c[tid] = w1[d * HH + tid];
        sb1c[tid] = b1[d * HH + tid];
        sb2c[tid] = b2[d * HH + tid];
    }
    if (tid < 64) sb3c[tid] = b3[d * EE + tid];

    for (int t = blockIdx.x; t < BB / 64; t += gridDim.x) {
        const int r0 = t * 64;
        __syncthreads();
        if (tid < 64) sx[tid] = x[(r0 + tid) * DD + d];
        __syncthreads();

        for (int i = tid; i < 64 * HH; i += 512) {
            int r = i >> 7, h = i & 127;
            sh1[r * ST + h] = fast_sin(fmaf(sx[r], sw1c[h], sb1c[h]));
        }
        __syncthreads();

        // GEMM1: 4 rows x 4 outputs, 4 K per step
        {
            ull acc[4][4];
            #pragma unroll
            for (int i = 0; i < 4; i++)
                #pragma unroll
                for (int s = 0; s < 4; s++) acc[i][s] = 0ull;

            const float* bp = sW2 + (kl + 64 * eh) * ST;
            const float* a0 = sh1 + tr0 * ST;
            #pragma unroll 2
            for (int h = 0; h < HH; h += 4) {
                ulonglong2 bv[4];
                #pragma unroll
                for (int s = 0; s < 4; s++) bv[s] = ld4(bp + s * 16 * ST + h);
                #pragma unroll
                for (int i = 0; i < 4; i++) {
                    ulonglong2 av = ld4(a0 + i * ST + h);
                    #pragma unroll
                    for (int s = 0; s < 4; s++) {
                        acc[i][s] = ffma2(av.x, bv[s].x, acc[i][s]);
                        acc[i][s] = ffma2(av.y, bv[s].y, acc[i][s]);
                    }
                }
            }
            #pragma unroll
            for (int i = 0; i < 4; i++)
                #pragma unroll
                for (int s = 0; s < 4; s++) {
                    float2 p = upk(acc[i][s]);
                    int k = kl + 16 * s + 64 * eh;
                    sh2[(tr0 + i) * ST + k] = fast_sin(p.x + p.y + sb2c[k]);
                }
        }
        __syncthreads();

        // GEMM2: 4 rows x 2 outputs, 4 K per step
        {
            ull acc[4][2];
            #pragma unroll
            for (int i = 0; i < 4; i++)
                #pragma unroll
                for (int s = 0; s < 2; s++)
                    acc[i][s] = pk2(sb3c[kl + 16 * s + 32 * eh], 0.f);

            const float* bp = sW3 + (kl + 32 * eh) * ST;
            const float* a0 = sh2 + tr0 * ST;
            #pragma unroll 2
            for (int h = 0; h < HH; h += 4) {
                ulonglong2 bv[2];
                #pragma unroll
                for (int s = 0; s < 2; s++) bv[s] = ld4(bp + s * 16 * ST + h);
                #pragma unroll
                for (int i = 0; i < 4; i++) {
                    ulonglong2 av = ld4(a0 + i * ST + h);
                    #pragma unroll
                    for (int s = 0; s < 2; s++) {
                        acc[i][s] = ffma2(av.x, bv[s].x, acc[i][s]);
                        acc[i][s] = ffma2(av.y, bv[s].y, acc[i][s]);
                    }
                }
            }
            #pragma unroll
            for (int i = 0; i < 4; i++)
                #pragma unroll
                for (int s = 0; s < 2; s++) {
                    float2 p = upk(acc[i][s]);
                    int e = kl + 16 * s + 32 * eh;
                    g_tok[((r0 + tr0 + i) * DD + d) * EE + e] = p.x + p.y;
                }
        }
    }
}

// ============================================================================
// MHA (folded): S += Wf_slice . (0.5*mean_i out_proj(attn)_i)
// LDS.128 proj + attention loops, strides 68.
// ============================================================================
#define SW 68          // stride for Wqk + q/k (mult of 4 for LDS.128)
#define SWT 68         // stride for stok
#define SMH 68         // stride for m_h rows
#define MHA_PREFIX_F (128*SW + 128 + 4*SMH + 64 + 8 + 2*32*SW + 8*64)  // 14040
#define MHA_SELF_F  (MHA_PREFIX_F + 32*SWT)   // 16216
#define MHA_CROSS_F (MHA_PREFIX_F + 64*SWT)   // 18392

template<int QOFF, int KVOFF, bool ACCUM, bool POOLB>
__global__ __launch_bounds__(256, 2)
void mha_kernel(const float* __restrict__ Win, const float* __restrict__ bin,
                const float* __restrict__ Wo,  const float* __restrict__ Wf)
{
    extern __shared__ float sm_[];
    float* sWqk = sm_;                   // [e][c] e<64: Wq, e>=64: Wk
    float* sbqk = sWqk + 128 * SW;       // 128
    float* smh  = sbqk + 128;            // [h][c] stride 68
    float* su   = smh + 4 * SMH;         // 64
    float* scb  = su + 64;               // 8
    float* sq   = scb + 8;               // [tr][68] (32 rows)
    float* sk   = sq + 32 * SW;
    float* satt = sk + 32 * SW;          // [br][64]
    float* stok = satt + 512;            // [trow][68]

    const int tid  = threadIdx.x;
    const int w    = tid >> 5, lane = tid & 31;
    const int kl   = lane & 15, sg = lane >> 4;
    const int eh   = w & 1;
    const int rgw  = w >> 1;
    const int tr0  = rgw * 8 + sg * 4;

    constexpr bool SELF = (QOFF == KVOFF);
    constexpr int FOFF = POOLB ? 64 : 0;

    for (int i = tid; i < 128 * 64; i += 256) {
        int e = i >> 6, c = i & 63;
        sWqk[e * SW + c] = Win[i];
    }
    if (tid < 128) sbqk[tid] = bin[tid];

    // u_c = sum_e Wf[FOFF+e] * Wo[e][c]
    if (tid < 64) {
        float s = 0.f;
        for (int e = 0; e < 64; e++) s = fmaf(Wf[FOFF + e], Wo[e * 64 + tid], s);
        su[tid] = s;
    }
    __syncthreads();

    // m_h[c] = sum_{cc in head h} u_cc * Wv[cc][c]
    {
        int h = tid >> 6, dd2 = tid & 63;
        float s = 0.f;
        #pragma unroll
        for (int cc = 0; cc < 16; cc++)
            s = fmaf(su[h * 16 + cc], Win[(128 + h * 16 + cc) * 64 + dd2], s);
        smh[h * SMH + dd2] = s;
    }
    if (tid == 0) {
        float s = 0.f;
        for (int c = 0; c < 64; c++) s = fmaf(su[c], bin[128 + c], s);
        scb[0] = 0.5f * s;
    }

    for (int t = blockIdx.x; t < BB / 8; t += gridDim.x) {
        const int r0 = t * 8;
        __syncthreads();

        // ---- float4 staging ----
        if (SELF) {
            #pragma unroll
            for (int i2 = 0; i2 < 2; i2++) {
                int i = tid + 256 * i2;
                int trow = i >> 4, c4 = i & 15;
                int br = trow >> 2, tk = trow & 3;
                float4 v = *(const float4*)(g_tok + (r0 + br) * 512 +
                                            (QOFF + tk) * 64 + c4 * 4);
                *(float4*)(stok + trow * SWT + c4 * 4) = v;
            }
        } else {
            const float4* src = (const float4*)(g_tok + r0 * 512);
            #pragma unroll
            for (int i2 = 0; i2 < 4; i2++) {
                int i = tid + 256 * i2;
                int trow = i >> 4, c4 = i & 15;
                float4 v = src[i];
                *(float4*)(stok + trow * SWT + c4 * 4) = v;
            }
        }
        __syncthreads();

        // ---- Q/K proj: thread = 4 rows x 4 outputs, 4 K per step ---------
        {
            ull acc[4][4];
            #pragma unroll
            for (int i = 0; i < 4; i++)
                #pragma unroll
                for (int s = 0; s < 4; s++)
                    acc[i][s] = pk2(sbqk[kl + 16 * s + 64 * eh], 0.f);

            const float* ap[4];
            #pragma unroll
            for (int i = 0; i < 4; i++) {
                int tr = tr0 + i, br = tr >> 2, tk = tr & 3;
                if (SELF) ap[i] = stok + tr * SWT;
                else      ap[i] = stok + (br * 8 + (eh ? KVOFF : QOFF) + tk) * SWT;
            }
            const float* bp = sWqk + (kl + 64 * eh) * SW;

            #pragma unroll 2
            for (int c = 0; c < 64; c += 4) {
                ulonglong2 bv[4];
                #pragma unroll
                for (int s = 0; s < 4; s++) bv[s] = ld4(bp + s * 16 * SW + c);
                #pragma unroll
                for (int i = 0; i < 4; i++) {
                    ulonglong2 av = ld4(ap[i] + c);
                    #pragma unroll
                    for (int s = 0; s < 4; s++) {
                        acc[i][s] = ffma2(av.x, bv[s].x, acc[i][s]);
                        acc[i][s] = ffma2(av.y, bv[s].y, acc[i][s]);
                    }
                }
            }
            float* dest = eh ? sk : sq;
            #pragma unroll
            for (int i = 0; i < 4; i++) {
                int trw = (tr0 + i) * SW;
                #pragma unroll
                for (int s = 0; s < 4; s++) {
                    float2 p = upk(acc[i][s]);
                    dest[trw + kl + 16 * s] = p.x + p.y;
                }
            }
        }
        __syncthreads();

        // ---- attention + folded pooling: warp w -> batch row w -----------
        {
            const float* sq_r = sq + w * 4 * SW;
            const float* sk_r = sk + w * 4 * SW;
            float* satt_r = satt + w * 64;

            float a01[2];
            #pragma unroll
            for (int z = 0; z < 2; z++) {
                int m = lane + 32 * z;
                int h = m >> 4, i = (m >> 2) & 3, j = m & 3;
                const float* qb = sq_r + i * SW + h * 16;
                const float* kb = sk_r + j * SW + h * 16;
                ull acc = 0ull;
                #pragma unroll
                for (int dd2 = 0; dd2 < 16; dd2 += 4) {
                    ulonglong2 qv = ld4(qb + dd2);
                    ulonglong2 kv = ld4(kb + dd2);
                    acc = ffma2(qv.x, kv.x, acc);
                    acc = ffma2(qv.y, kv.y, acc);
                }
                float2 p = upk(acc);
                a01[z] = (p.x + p.y) * 0.25f;
            }
            float m0 = a01[0], m1 = a01[1];
            m0 = fmaxf(m0, __shfl_xor_sync(0xffffffffu, m0, 1));
            m0 = fmaxf(m0, __shfl_xor_sync(0xffffffffu, m0, 2));
            m1 = fmaxf(m1, __shfl_xor_sync(0xffffffffu, m1, 1));
            m1 = fmaxf(m1, __shfl_xor_sync(0xffffffffu, m1, 2));
            float e0 = __expf(a01[0] - m0), e1 = __expf(a01[1] - m1);
            float s0 = e0, s1 = e1;
            s0 += __shfl_xor_sync(0xffffffffu, s0, 1);
            s0 += __shfl_xor_sync(0xffffffffu, s0, 2);
            s1 += __shfl_xor_sync(0xffffffffu, s1, 1);
            s1 += __shfl_xor_sync(0xffffffffu, s1, 2);
            satt_r[lane]      = __fdividef(e0, s0);
            satt_r[lane + 32] = __fdividef(e1, s1);
            __syncwarp();

            // lanes 0..15: pair (h = lane>>2, j = lane&3)
            float part = 0.f;
            {
                int h = lane >> 2, j = lane & 3;
                int kvrow = SELF ? (w * 4 + j) : (w * 8 + KVOFF + j);
                const float* mh = smh + h * SMH;
                const float* tj = stok + kvrow * SWT;
                ull acc = 0ull;
                #pragma unroll
                for (int c = 0; c < 64; c += 4) {
                    ulonglong2 mv = ld4(mh + c);
                    ulonglong2 tv = ld4(tj + c);
                    acc = ffma2(mv.x, tv.x, acc);
                    acc = ffma2(mv.y, tv.y, acc);
                }
                float2 p = upk(acc);
                float sjh = p.x + p.y;
                float wbar = satt_r[h * 16 + j]     + satt_r[h * 16 + 4 + j] +
                             satt_r[h * 16 + 8 + j] + satt_r[h * 16 + 12 + j];
                part = wbar * sjh;
                if (lane >= 16) part = 0.f;
            }
            part += __shfl_down_sync(0xffffffffu, part, 8);
            part += __shfl_down_sync(0xffffffffu, part, 4);
            part += __shfl_down_sync(0xffffffffu, part, 2);
            part += __shfl_down_sync(0xffffffffu, part, 1);
            if (lane == 0) {
                float S = 0.125f * part + scb[0];
                if (ACCUM) g_S[r0 + w] += S;
                else       g_S[r0 + w]  = S;
            }
        }
    }
}

// ---------------- epilogue: out = leaky(S + C) ------------------------------
__global__ __launch_bounds__(256)
void epi_kernel(const float* __restrict__ Wf, const float* __restrict__ bf,
                const float* __restrict__ bo_sa, const float* __restrict__ bo_sb,
                const float* __restrict__ bo_ca, const float* __restrict__ bo_cb,
                float* __restrict__ out)
{
    int b = blockIdx.x * blockDim.x + threadIdx.x;
    if (b >= BB) return;
    float C = bf[0];
    #pragma unroll 4
    for (int e = 0; e < 64; e++) {
        C = fmaf(0.5f * Wf[e],      bo_sa[e] + bo_ca[e], C);
        C = fmaf(0.5f * Wf[64 + e], bo_sb[e] + bo_cb[e], C);
    }
    float s = g_S[b] + C;
    out[b] = (s > 0.f) ? s : 0.01f * s;
}

// ---------------- launch ----------------------------------------------------
static const int A_SMEM   = TOK_SMEM_F * 4;
static const int M_SMEM_S = MHA_SELF_F * 4;
static const int M_SMEM_C = MHA_CROSS_F * 4;

extern "C" void kernel_launch(void* const* d_in, const int* in_sizes, int n_in,
                              void* d_out, int out_size)
{
    (void)in_sizes; (void)n_in; (void)out_size;
    const float* x  = (const float*)d_in[0];
    const float* w1 = (const float*)d_in[1];
    const float* b1 = (const float*)d_in[2];
    const float* w2 = (const float*)d_in[3];
    const float* b2 = (const float*)d_in[4];
    const float* w3 = (const float*)d_in[5];
    const float* b3 = (const float*)d_in[6];
    const float* Win_sa = (const float*)d_in[7];
    const float* bin_sa = (const float*)d_in[8];
    const float* Wo_sa  = (const float*)d_in[9];
    const float* bo_sa  = (const float*)d_in[10];
    const float* Win_sb = (const float*)d_in[11];
    const float* bin_sb = (const float*)d_in[12];
    const float* Wo_sb  = (const float*)d_in[13];
    const float* bo_sb  = (const float*)d_in[14];
    const float* Win_ca = (const float*)d_in[15];
    const float* bin_ca = (const float*)d_in[16];
    const float* Wo_ca  = (const float*)d_in[17];
    const float* bo_ca  = (const float*)d_in[18];
    const float* Win_cb = (const float*)d_in[19];
    const float* bin_cb = (const float*)d_in[20];
    const float* Wo_cb  = (const float*)d_in[21];
    const float* bo_cb  = (const float*)d_in[22];
    const float* Wf = (const float*)d_in[23];
    const float* bf = (const float*)d_in[24];
    float* out = (float*)d_out;

    cudaFuncSetAttribute(tok_kernel, cudaFuncAttributeMaxDynamicSharedMemorySize, A_SMEM);
    cudaFuncSetAttribute(mha_kernel<0, 0, false, false>, cudaFuncAttributeMaxDynamicSharedMemorySize, M_SMEM_S);
    cudaFuncSetAttribute(mha_kernel<4, 4, true,  true>,  cudaFuncAttributeMaxDynamicSharedMemorySize, M_SMEM_S);
    cudaFuncSetAttribute(mha_kernel<0, 4, true,  false>, cudaFuncAttributeMaxDynamicSharedMemorySize, M_SMEM_C);
    cudaFuncSetAttribute(mha_kernel<4, 0, true,  true>,  cudaFuncAttributeMaxDynamicSharedMemorySize, M_SMEM_C);

    tok_kernel<<<dim3(37, 8), 512, A_SMEM>>>(x, w1, b1, w2, b2, w3, b3);

    mha_kernel<0, 0, false, false><<<296, 256, M_SMEM_S>>>(Win_sa, bin_sa, Wo_sa, Wf);
    mha_kernel<4, 4, true,  true ><<<296, 256, M_SMEM_S>>>(Win_sb, bin_sb, Wo_sb, Wf);
    mha_kernel<0, 4, true,  false><<<296, 256, M_SMEM_C>>>(Win_ca, bin_ca, Wo_ca, Wf);
    mha_kernel<4, 0, true,  true ><<<296, 256, M_SMEM_C>>>(Win_cb, bin_cb, Wo_cb, Wf);

    epi_kernel<<<BB / 256, 256>>>(Wf, bf, bo_sa, bo_sb, bo_ca, bo_cb, out);
}

// round 10
// speedup vs baseline: 1.6048x; 1.0022x over previous
#include <cuda_runtime.h>

#define BB 65536
#define DD 8
#define HH 128
#define EE 64

typedef unsigned long long ull;

__device__ __forceinline__ ull ffma2(ull a, ull b, ull c) {
    ull d;
    asm("fma.rn.f32x2 %0,%1,%2,%3;" : "=l"(d) : "l"(a), "l"(b), "l"(c));
    return d;
}
__device__ __forceinline__ ull pk2(float lo, float hi) {
    ull r;
    asm("mov.b64 %0,{%1,%2};" : "=l"(r) : "f"(lo), "f"(hi));
    return r;
}
__device__ __forceinline__ float2 upk(ull v) {
    float2 r;
    asm("mov.b64 {%0,%1},%2;" : "=f"(r.x), "=f"(r.y) : "l"(v));
    return r;
}
__device__ __forceinline__ ull ld2(const float* p) {
    return *(const ull*)p;
}
__device__ __forceinline__ ulonglong2 ld4(const float* p) {
    return *(const ulonglong2*)p;
}

// FFMA-only sin: reduce to [-pi,pi], degree-11 odd minimax.
__device__ __forceinline__ float fast_sin(float x) {
    float k = rintf(x * 0.15915494309f);
    float r = fmaf(k, -6.2831855f, x);
    r = fmaf(k, 1.7484555e-7f, r);
    float r2 = r * r;
    float p = -2.3889859e-8f;
    p = fmaf(p, r2, 2.7525562e-6f);
    p = fmaf(p, r2, -1.9840874e-4f);
    p = fmaf(p, r2, 8.3333310e-3f);
    p = fmaf(p, r2, -1.6666667e-1f);
    p = fmaf(p, r2, 1.0f);
    return r * p;
}

// ---------------- scratch ---------------------------------------------------
__device__ float g_tok[BB * DD * EE];   // [b][token d][o]
__device__ float g_S[BB];               // folded scalar accumulator

// ============================================================================
// Kernel A: tokens = W3 sin(W2 sin(x*w1+b1)+b2)+b3  (unchanged from R9)
// ============================================================================
#define ST 132
#define TOK_SMEM_F (320*ST + 128*3 + 64 + 64)   // 42752

__global__ __launch_bounds__(512, 1)
void tok_kernel(const float* __restrict__ x,
                const float* __restrict__ w1, const float* __restrict__ b1,
                const float* __restrict__ w2, const float* __restrict__ b2,
                const float* __restrict__ w3, const float* __restrict__ b3)
{
    extern __shared__ float sm[];
    float* sW2  = sm;                    // [k][h] native, stride 132
    float* sW3  = sW2 + 128 * ST;
    float* sh1  = sW3 + 64 * ST;
    float* sh2  = sh1 + 64 * ST;
    float* sw1c = sh2 + 64 * ST;
    float* sb1c = sw1c + 128;
    float* sb2c = sb1c + 128;
    float* sb3c = sb2c + 128;
    float* sx   = sb3c + 64;

    const int d    = blockIdx.y;
    const int tid  = threadIdx.x;
    const int w    = tid >> 5, lane = tid & 31;
    const int kl   = lane & 15, sg = lane >> 4;
    const int eh   = w & 1;
    const int rgw  = w >> 1;
    const int tr0  = rgw * 8 + sg * 4;

    for (int i = tid; i < HH * HH; i += 512) {
        int k = i >> 7, h = i & 127;
        sW2[k * ST + h] = w2[d * HH * HH + i];
    }
    for (int i = tid; i < EE * HH; i += 512) {
        int o = i >> 7, h = i & 127;
        sW3[o * ST + h] = w3[d * EE * HH + i];
    }
    if (tid < 128) {
        sw1c[tid] = w1[d * HH + tid];
        sb1c[tid] = b1[d * HH + tid];
        sb2c[tid] = b2[d * HH + tid];
    }
    if (tid < 64) sb3c[tid] = b3[d * EE + tid];

    for (int t = blockIdx.x; t < BB / 64; t += gridDim.x) {
        const int r0 = t * 64;
        __syncthreads();
        if (tid < 64) sx[tid] = x[(r0 + tid) * DD + d];
        __syncthreads();

        for (int i = tid; i < 64 * HH; i += 512) {
            int r = i >> 7, h = i & 127;
            sh1[r * ST + h] = fast_sin(fmaf(sx[r], sw1c[h], sb1c[h]));
        }
        __syncthreads();

        // GEMM1
        {
            ull acc[4][4];
            #pragma unroll
            for (int i = 0; i < 4; i++)
                #pragma unroll
                for (int s = 0; s < 4; s++) acc[i][s] = 0ull;

            const float* bp = sW2 + (kl + 64 * eh) * ST;
            const float* a0 = sh1 + tr0 * ST;
            #pragma unroll 2
            for (int h = 0; h < HH; h += 4) {
                ulonglong2 bv[4];
                #pragma unroll
                for (int s = 0; s < 4; s++) bv[s] = ld4(bp + s * 16 * ST + h);
                #pragma unroll
                for (int i = 0; i < 4; i++) {
                    ulonglong2 av = ld4(a0 + i * ST + h);
                    #pragma unroll
                    for (int s = 0; s < 4; s++) {
                        acc[i][s] = ffma2(av.x, bv[s].x, acc[i][s]);
                        acc[i][s] = ffma2(av.y, bv[s].y, acc[i][s]);
                    }
                }
            }
            #pragma unroll
            for (int i = 0; i < 4; i++)
                #pragma unroll
                for (int s = 0; s < 4; s++) {
                    float2 p = upk(acc[i][s]);
                    int k = kl + 16 * s + 64 * eh;
                    sh2[(tr0 + i) * ST + k] = fast_sin(p.x + p.y + sb2c[k]);
                }
        }
        __syncthreads();

        // GEMM2
        {
            ull acc[4][2];
            #pragma unroll
            for (int i = 0; i < 4; i++)
                #pragma unroll
                for (int s = 0; s < 2; s++)
                    acc[i][s] = pk2(sb3c[kl + 16 * s + 32 * eh], 0.f);

            const float* bp = sW3 + (kl + 32 * eh) * ST;
            const float* a0 = sh2 + tr0 * ST;
            #pragma unroll 2
            for (int h = 0; h < HH; h += 4) {
                ulonglong2 bv[2];
                #pragma unroll
                for (int s = 0; s < 2; s++) bv[s] = ld4(bp + s * 16 * ST + h);
                #pragma unroll
                for (int i = 0; i < 4; i++) {
                    ulonglong2 av = ld4(a0 + i * ST + h);
                    #pragma unroll
                    for (int s = 0; s < 2; s++) {
                        acc[i][s] = ffma2(av.x, bv[s].x, acc[i][s]);
                        acc[i][s] = ffma2(av.y, bv[s].y, acc[i][s]);
                    }
                }
            }
            #pragma unroll
            for (int i = 0; i < 4; i++)
                #pragma unroll
                for (int s = 0; s < 2; s++) {
                    float2 p = upk(acc[i][s]);
                    int e = kl + 16 * s + 32 * eh;
                    g_tok[((r0 + tr0 + i) * DD + d) * EE + e] = p.x + p.y;
                }
        }
    }
}

// ============================================================================
// MHA (folded): tile 16 batch rows, proj 8-row register tile, shuffle pooling.
// ============================================================================
#define SW 68
#define SWT 68
#define SMH 68
// sWqk 128*68 | sbqk 128 | smh 4*68 | su 64 | scb 8 | sq 64*68 | sk 64*68 | stok
#define MHA_PREFIX_F (128*SW + 128 + 4*SMH + 64 + 8 + 2*64*SW)   // 17880
#define MHA_SELF_F  (MHA_PREFIX_F + 64*SWT)    // 22232  (88.9 KB)
#define MHA_CROSS_F (MHA_PREFIX_F + 128*SWT)   // 26584  (106.3 KB)

template<int QOFF, int KVOFF, bool ACCUM, bool POOLB>
__global__ __launch_bounds__(256, 2)
void mha_kernel(const float* __restrict__ Win, const float* __restrict__ bin,
                const float* __restrict__ Wo,  const float* __restrict__ Wf)
{
    extern __shared__ float sm_[];
    float* sWqk = sm_;                   // [e][c] e<64: Wq, e>=64: Wk
    float* sbqk = sWqk + 128 * SW;       // 128
    float* smh  = sbqk + 128;            // [h][c] stride 68
    float* su   = smh + 4 * SMH;         // 64
    float* scb  = su + 64;               // 8
    float* sq   = scb + 8;               // [tr][68] (64 token-rows)
    float* sk   = sq + 64 * SW;
    float* stok = sk + 64 * SW;          // [srow][68] (64 self / 128 cross)

    const int tid  = threadIdx.x;
    const int w    = tid >> 5, lane = tid & 31;
    const int kl   = lane & 15, sg = lane >> 4;
    const int eh   = w & 1;              // 0 = Q, 1 = K
    const int rgw  = w >> 1;             // 0..3
    // thread's 8 token-rows: base + (i&3) + (i>>2)*8, base multiple of 4
    const int base = rgw * 16 + sg * 4;

    constexpr bool SELF = (QOFF == KVOFF);
    constexpr int FOFF = POOLB ? 64 : 0;

    for (int i = tid; i < 128 * 64; i += 256) {
        int e = i >> 6, c = i & 63;
        sWqk[e * SW + c] = Win[i];
    }
    if (tid < 128) sbqk[tid] = bin[tid];

    // u_c = sum_e Wf[FOFF+e] * Wo[e][c]
    if (tid < 64) {
        float s = 0.f;
        for (int e = 0; e < 64; e++) s = fmaf(Wf[FOFF + e], Wo[e * 64 + tid], s);
        su[tid] = s;
    }
    __syncthreads();

    // m_h[c] = sum_{cc in head h} u_cc * Wv[cc][c]
    {
        int h = tid >> 6, dd2 = tid & 63;
        float s = 0.f;
        #pragma unroll
        for (int cc = 0; cc < 16; cc++)
            s = fmaf(su[h * 16 + cc], Win[(128 + h * 16 + cc) * 64 + dd2], s);
        smh[h * SMH + dd2] = s;
    }
    if (tid == 0) {
        float s = 0.f;
        for (int c = 0; c < 64; c++) s = fmaf(su[c], bin[128 + c], s);
        scb[0] = 0.5f * s;
    }

    for (int t = blockIdx.x; t < BB / 16; t += gridDim.x) {
        const int r0 = t * 16;
        __syncthreads();   // prev tile fully consumed

        // ---- float4 staging ------------------------------------------------
        if (SELF) {
            #pragma unroll
            for (int i2 = 0; i2 < 4; i2++) {
                int i = tid + 256 * i2;          // 0..1023 float4s
                int trow = i >> 4, c4 = i & 15;  // trow = br*4+tk
                int br = trow >> 2, tk = trow & 3;
                float4 v = *(const float4*)(g_tok + (r0 + br) * 512 +
                                            (QOFF + tk) * 64 + c4 * 4);
                *(float4*)(stok + trow * SWT + c4 * 4) = v;
            }
        } else {
            const float4* src = (const float4*)(g_tok + r0 * 512);
            #pragma unroll
            for (int i2 = 0; i2 < 8; i2++) {
                int i = tid + 256 * i2;          // 0..2047 float4s
                int trow = i >> 4, c4 = i & 15;  // trow = br*8+tk
                float4 v = src[i];
                *(float4*)(stok + trow * SWT + c4 * 4) = v;
            }
        }
        __syncthreads();

        // ---- Q/K proj: thread = 8 token-rows x 4 outputs -------------------
        {
            ull acc[8][4];
            #pragma unroll
            for (int i = 0; i < 8; i++)
                #pragma unroll
                for (int s = 0; s < 4; s++)
                    acc[i][s] = pk2(sbqk[kl + 16 * s + 64 * eh], 0.f);

            const int off = eh ? KVOFF : QOFF;
            const float* ap[8];
            #pragma unroll
            for (int i = 0; i < 8; i++) {
                int tr = base + (i & 3) + (i >> 2) * 8;
                int row;
                if (SELF) row = tr;
                else      row = (tr >> 2) * 8 + off + (tr & 3);
                ap[i] = stok + row * SWT;
            }
            const float* bp = sWqk + (kl + 64 * eh) * SW;

            #pragma unroll 2
            for (int c = 0; c < 64; c += 4) {
                ulonglong2 bv[4];
                #pragma unroll
                for (int s = 0; s < 4; s++) bv[s] = ld4(bp + s * 16 * SW + c);
                #pragma unroll
                for (int i = 0; i < 8; i++) {
                    ulonglong2 av = ld4(ap[i] + c);
                    #pragma unroll
                    for (int s = 0; s < 4; s++) {
                        acc[i][s] = ffma2(av.x, bv[s].x, acc[i][s]);
                        acc[i][s] = ffma2(av.y, bv[s].y, acc[i][s]);
                    }
                }
            }
            float* dest = eh ? sk : sq;
            #pragma unroll
            for (int i = 0; i < 8; i++) {
                int trw = (base + (i & 3) + (i >> 2) * 8) * SW;
                #pragma unroll
                for (int s = 0; s < 4; s++) {
                    float2 p = upk(acc[i][s]);
                    dest[trw + kl + 16 * s] = p.x + p.y;
                }
            }
        }
        __syncthreads();

        // ---- attention + folded pooling: warp w -> batch rows w, w+8 ------
        #pragma unroll
        for (int rr = 0; rr < 2; rr++) {
            int br = w + rr * 8;
            const float* sq_r = sq + br * 4 * SW;
            const float* sk_r = sk + br * 4 * SW;

            float a01[2];
            #pragma unroll
            for (int z = 0; z < 2; z++) {
                int m = lane + 32 * z;
                int h = m >> 4, i = (m >> 2) & 3, j = m & 3;
                const float* qb = sq_r + i * SW + h * 16;
                const float* kb = sk_r + j * SW + h * 16;
                ull acc = 0ull;
                #pragma unroll
                for (int dd2 = 0; dd2 < 16; dd2 += 4) {
                    ulonglong2 qv = ld4(qb + dd2);
                    ulonglong2 kv = ld4(kb + dd2);
                    acc = ffma2(qv.x, kv.x, acc);
                    acc = ffma2(qv.y, kv.y, acc);
                }
                float2 p = upk(acc);
                a01[z] = (p.x + p.y) * 0.25f;
            }
            float m0 = a01[0], m1 = a01[1];
            m0 = fmaxf(m0, __shfl_xor_sync(0xffffffffu, m0, 1));
            m0 = fmaxf(m0, __shfl_xor_sync(0xffffffffu, m0, 2));
            m1 = fmaxf(m1, __shfl_xor_sync(0xffffffffu, m1, 1));
            m1 = fmaxf(m1, __shfl_xor_sync(0xffffffffu, m1, 2));
            float e0 = __expf(a01[0] - m0), e1 = __expf(a01[1] - m1);
            float s0 = e0, s1 = e1;
            s0 += __shfl_xor_sync(0xffffffffu, s0, 1);
            s0 += __shfl_xor_sync(0xffffffffu, s0, 2);
            s1 += __shfl_xor_sync(0xffffffffu, s1, 1);
            s1 += __shfl_xor_sync(0xffffffffu, s1, 2);
            float p0 = __fdividef(e0, s0);     // att for m = lane   (h 0..1)
            float p1 = __fdividef(e1, s1);     // att for m = lane+32 (h 2..3)

            // i-sums via shuffles: w0[lane] = sum_i att[h(lane),i,j(lane)]
            float w0 = p0 + __shfl_xor_sync(0xffffffffu, p0, 4);
            w0 += __shfl_xor_sync(0xffffffffu, w0, 8);
            float w1 = p1 + __shfl_xor_sync(0xffffffffu, p1, 4);
            w1 += __shfl_xor_sync(0xffffffffu, w1, 8);

            // pool: lanes 0..15 hold (h = lane>>2, j = lane&3)
            int h = lane >> 2, j = lane & 3;
            int src = (h & 1) * 16 + j;
            float wa = __shfl_sync(0xffffffffu, w0, src);
            float wbv = __shfl_sync(0xffffffffu, w1, src);
            float wbar = (h < 2) ? wa : wbv;

            float part = 0.f;
            {
                int kvrow = SELF ? (br * 4 + j) : (br * 8 + KVOFF + j);
                const float* mh = smh + h * SMH;
                const float* tj = stok + kvrow * SWT;
                ull acc = 0ull;
                #pragma unroll
                for (int c = 0; c < 64; c += 4) {
                    ulonglong2 mv = ld4(mh + c);
                    ulonglong2 tv = ld4(tj + c);
                    acc = ffma2(mv.x, tv.x, acc);
                    acc = ffma2(mv.y, tv.y, acc);
                }
                float2 p = upk(acc);
                part = wbar * (p.x + p.y);
                if (lane >= 16) part = 0.f;
            }
            part += __shfl_down_sync(0xffffffffu, part, 8);
            part += __shfl_down_sync(0xffffffffu, part, 4);
            part += __shfl_down_sync(0xffffffffu, part, 2);
            part += __shfl_down_sync(0xffffffffu, part, 1);
            if (lane == 0) {
                float S = 0.125f * part + scb[0];
                if (ACCUM) g_S[r0 + br] += S;
                else       g_S[r0 + br]  = S;
            }
        }
    }
}

// ---------------- epilogue: out = leaky(S + C) ------------------------------
__global__ __launch_bounds__(256)
void epi_kernel(const float* __restrict__ Wf, const float* __restrict__ bf,
                const float* __restrict__ bo_sa, const float* __restrict__ bo_sb,
                const float* __restrict__ bo_ca, const float* __restrict__ bo_cb,
                float* __restrict__ out)
{
    int b = blockIdx.x * blockDim.x + threadIdx.x;
    if (b >= BB) return;
    float C = bf[0];
    #pragma unroll 4
    for (int e = 0; e < 64; e++) {
        C = fmaf(0.5f * Wf[e],      bo_sa[e] + bo_ca[e], C);
        C = fmaf(0.5f * Wf[64 + e], bo_sb[e] + bo_cb[e], C);
    }
    float s = g_S[b] + C;
    out[b] = (s > 0.f) ? s : 0.01f * s;
}

// ---------------- launch ----------------------------------------------------
static const int A_SMEM   = TOK_SMEM_F * 4;
static const int M_SMEM_S = MHA_SELF_F * 4;
static const int M_SMEM_C = MHA_CROSS_F * 4;

extern "C" void kernel_launch(void* const* d_in, const int* in_sizes, int n_in,
                              void* d_out, int out_size)
{
    (void)in_sizes; (void)n_in; (void)out_size;
    const float* x  = (const float*)d_in[0];
    const float* w1 = (const float*)d_in[1];
    const float* b1 = (const float*)d_in[2];
    const float* w2 = (const float*)d_in[3];
    const float* b2 = (const float*)d_in[4];
    const float* w3 = (const float*)d_in[5];
    const float* b3 = (const float*)d_in[6];
    const float* Win_sa = (const float*)d_in[7];
    const float* bin_sa = (const float*)d_in[8];
    const float* Wo_sa  = (const float*)d_in[9];
    const float* bo_sa  = (const float*)d_in[10];
    const float* Win_sb = (const float*)d_in[11];
    const float* bin_sb = (const float*)d_in[12];
    const float* Wo_sb  = (const float*)d_in[13];
    const float* bo_sb  = (const float*)d_in[14];
    const float* Win_ca = (const float*)d_in[15];
    const float* bin_ca = (const float*)d_in[16];
    const float* Wo_ca  = (const float*)d_in[17];
    const float* bo_ca  = (const float*)d_in[18];
    const float* Win_cb = (const float*)d_in[19];
    const float* bin_cb = (const float*)d_in[20];
    const float* Wo_cb  = (const float*)d_in[21];
    const float* bo_cb  = (const float*)d_in[22];
    const float* Wf = (const float*)d_in[23];
    const float* bf = (const float*)d_in[24];
    float* out = (float*)d_out;

    cudaFuncSetAttribute(tok_kernel, cudaFuncAttributeMaxDynamicSharedMemorySize, A_SMEM);
    cudaFuncSetAttribute(mha_kernel<0, 0, false, false>, cudaFuncAttributeMaxDynamicSharedMemorySize, M_SMEM_S);
    cudaFuncSetAttribute(mha_kernel<4, 4, true,  true>,  cudaFuncAttributeMaxDynamicSharedMemorySize, M_SMEM_S);
    cudaFuncSetAttribute(mha_kernel<0, 4, true,  false>, cudaFuncAttributeMaxDynamicSharedMemorySize, M_SMEM_C);
    cudaFuncSetAttribute(mha_kernel<4, 0, true,  true>,  cudaFuncAttributeMaxDynamicSharedMemorySize, M_SMEM_C);

    tok_kernel<<<dim3(37, 8), 512, A_SMEM>>>(x, w1, b1, w2, b2, w3, b3);

    mha_kernel<0, 0, false, false><<<296, 256, M_SMEM_S>>>(Win_sa, bin_sa, Wo_sa, Wf);
    mha_kernel<4, 4, true,  true ><<<296, 256, M_SMEM_S>>>(Win_sb, bin_sb, Wo_sb, Wf);
    mha_kernel<0, 4, true,  false><<<296, 256, M_SMEM_C>>>(Win_ca, bin_ca, Wo_ca, Wf);
    mha_kernel<4, 0, true,  true ><<<296, 256, M_SMEM_C>>>(Win_cb, bin_cb, Wo_cb, Wf);

    epi_kernel<<<BB / 256, 256>>>(Wf, bf, bo_sa, bo_sb, bo_ca, bo_cb, out);
}

// round 11
// speedup vs baseline: 1.6647x; 1.0373x over previous
#include <cuda_runtime.h>

#define BB 65536
#define DD 8
#define HH 128
#define EE 64

typedef unsigned long long ull;

__device__ __forceinline__ ull ffma2(ull a, ull b, ull c) {
    ull d;
    asm("fma.rn.f32x2 %0,%1,%2,%3;" : "=l"(d) : "l"(a), "l"(b), "l"(c));
    return d;
}
__device__ __forceinline__ ull pk2(float lo, float hi) {
    ull r;
    asm("mov.b64 %0,{%1,%2};" : "=l"(r) : "f"(lo), "f"(hi));
    return r;
}
__device__ __forceinline__ float2 upk(ull v) {
    float2 r;
    asm("mov.b64 {%0,%1},%2;" : "=f"(r.x), "=f"(r.y) : "l"(v));
    return r;
}
__device__ __forceinline__ ulonglong2 ld4(const float* p) {
    return *(const ulonglong2*)p;
}
__device__ __forceinline__ void cpa16(float* sdst, const float* gsrc) {
    unsigned sa = (unsigned)__cvta_generic_to_shared(sdst);
    asm volatile("cp.async.cg.shared.global [%0], [%1], 16;" :: "r"(sa), "l"(gsrc));
}
#define CP_COMMIT() asm volatile("cp.async.commit_group;" ::: "memory")
#define CP_WAIT1()  asm volatile("cp.async.wait_group 1;" ::: "memory")

// FFMA-only sin: reduce to [-pi,pi], degree-11 odd minimax.
__device__ __forceinline__ float fast_sin(float x) {
    float k = rintf(x * 0.15915494309f);
    float r = fmaf(k, -6.2831855f, x);
    r = fmaf(k, 1.7484555e-7f, r);
    float r2 = r * r;
    float p = -2.3889859e-8f;
    p = fmaf(p, r2, 2.7525562e-6f);
    p = fmaf(p, r2, -1.9840874e-4f);
    p = fmaf(p, r2, 8.3333310e-3f);
    p = fmaf(p, r2, -1.6666667e-1f);
    p = fmaf(p, r2, 1.0f);
    return r * p;
}

// ---------------- scratch ---------------------------------------------------
__device__ float g_tok[BB * DD * EE];   // [b][token d][o]
__device__ float g_S[BB];               // folded scalar accumulator

// ============================================================================
// Kernel A: tokens = W3 sin(W2 sin(x*w1+b1)+b2)+b3  (unchanged)
// ============================================================================
#define ST 132
#define TOK_SMEM_F (320*ST + 128*3 + 64 + 64)   // 42752

__global__ __launch_bounds__(512, 1)
void tok_kernel(const float* __restrict__ x,
                const float* __restrict__ w1, const float* __restrict__ b1,
                const float* __restrict__ w2, const float* __restrict__ b2,
                const float* __restrict__ w3, const float* __restrict__ b3)
{
    extern __shared__ float sm[];
    float* sW2  = sm;                    // [k][h] native, stride 132
    float* sW3  = sW2 + 128 * ST;
    float* sh1  = sW3 + 64 * ST;
    float* sh2  = sh1 + 64 * ST;
    float* sw1c = sh2 + 64 * ST;
    float* sb1c = sw1c + 128;
    float* sb2c = sb1c + 128;
    float* sb3c = sb2c + 128;
    float* sx   = sb3c + 64;

    const int d    = blockIdx.y;
    const int tid  = threadIdx.x;
    const int w    = tid >> 5, lane = tid & 31;
    const int kl   = lane & 15, sg = lane >> 4;
    const int eh   = w & 1;
    const int rgw  = w >> 1;
    const int tr0  = rgw * 8 + sg * 4;

    for (int i = tid; i < HH * HH; i += 512) {
        int k = i >> 7, h = i & 127;
        sW2[k * ST + h] = w2[d * HH * HH + i];
    }
    for (int i = tid; i < EE * HH; i += 512) {
        int o = i >> 7, h = i & 127;
        sW3[o * ST + h] = w3[d * EE * HH + i];
    }
    if (tid < 128) {
        sw1c[tid] = w1[d * HH + tid];
        sb1c[tid] = b1[d * HH + tid];
        sb2c[tid] = b2[d * HH + tid];
    }
    if (tid < 64) sb3c[tid] = b3[d * EE + tid];

    for (int t = blockIdx.x; t < BB / 64; t += gridDim.x) {
        const int r0 = t * 64;
        __syncthreads();
        if (tid < 64) sx[tid] = x[(r0 + tid) * DD + d];
        __syncthreads();

        for (int i = tid; i < 64 * HH; i += 512) {
            int r = i >> 7, h = i & 127;
            sh1[r * ST + h] = fast_sin(fmaf(sx[r], sw1c[h], sb1c[h]));
        }
        __syncthreads();

        // GEMM1
        {
            ull acc[4][4];
            #pragma unroll
            for (int i = 0; i < 4; i++)
                #pragma unroll
                for (int s = 0; s < 4; s++) acc[i][s] = 0ull;

            const float* bp = sW2 + (kl + 64 * eh) * ST;
            const float* a0 = sh1 + tr0 * ST;
            #pragma unroll 2
            for (int h = 0; h < HH; h += 4) {
                ulonglong2 bv[4];
                #pragma unroll
                for (int s = 0; s < 4; s++) bv[s] = ld4(bp + s * 16 * ST + h);
                #pragma unroll
                for (int i = 0; i < 4; i++) {
                    ulonglong2 av = ld4(a0 + i * ST + h);
                    #pragma unroll
                    for (int s = 0; s < 4; s++) {
                        acc[i][s] = ffma2(av.x, bv[s].x, acc[i][s]);
                        acc[i][s] = ffma2(av.y, bv[s].y, acc[i][s]);
                    }
                }
            }
            #pragma unroll
            for (int i = 0; i < 4; i++)
                #pragma unroll
                for (int s = 0; s < 4; s++) {
                    float2 p = upk(acc[i][s]);
                    int k = kl + 16 * s + 64 * eh;
                    sh2[(tr0 + i) * ST + k] = fast_sin(p.x + p.y + sb2c[k]);
                }
        }
        __syncthreads();

        // GEMM2
        {
            ull acc[4][2];
            #pragma unroll
            for (int i = 0; i < 4; i++)
                #pragma unroll
                for (int s = 0; s < 2; s++)
                    acc[i][s] = pk2(sb3c[kl + 16 * s + 32 * eh], 0.f);

            const float* bp = sW3 + (kl + 32 * eh) * ST;
            const float* a0 = sh2 + tr0 * ST;
            #pragma unroll 2
            for (int h = 0; h < HH; h += 4) {
                ulonglong2 bv[2];
                #pragma unroll
                for (int s = 0; s < 2; s++) bv[s] = ld4(bp + s * 16 * ST + h);
                #pragma unroll
                for (int i = 0; i < 4; i++) {
                    ulonglong2 av = ld4(a0 + i * ST + h);
                    #pragma unroll
                    for (int s = 0; s < 2; s++) {
                        acc[i][s] = ffma2(av.x, bv[s].x, acc[i][s]);
                        acc[i][s] = ffma2(av.y, bv[s].y, acc[i][s]);
                    }
                }
            }
            #pragma unroll
            for (int i = 0; i < 4; i++)
                #pragma unroll
                for (int s = 0; s < 2; s++) {
                    float2 p = upk(acc[i][s]);
                    int e = kl + 16 * s + 32 * eh;
                    g_tok[((r0 + tr0 + i) * DD + d) * EE + e] = p.x + p.y;
                }
        }
    }
}

// ============================================================================
// MHA (folded): tile 8 rows, cp.async double-buffered staging, shuffle pooling.
// ============================================================================
#define SW 68
#define SWT 68
#define SMH 68
// sWqk 128*68 | sbqk 128 | smh 4*68 | su 64 | scb 8 | sq 32*68 | sk 32*68 | stok x2
#define MHA_PREFIX_F (128*SW + 128 + 4*SMH + 64 + 8 + 2*32*SW)   // 13528
#define MHA_SELF_F  (MHA_PREFIX_F + 2*32*SWT)   // 17880 (71.5 KB)
#define MHA_CROSS_F (MHA_PREFIX_F + 2*64*SWT)   // 22232 (88.9 KB)

template<int QOFF, int KVOFF, bool ACCUM, bool POOLB>
__global__ __launch_bounds__(256, 2)
void mha_kernel(const float* __restrict__ Win, const float* __restrict__ bin,
                const float* __restrict__ Wo,  const float* __restrict__ Wf)
{
    extern __shared__ float sm_[];
    float* sWqk  = sm_;                  // [e][c] e<64: Wq, e>=64: Wk
    float* sbqk  = sWqk + 128 * SW;      // 128
    float* smh   = sbqk + 128;           // [h][c]
    float* su    = smh + 4 * SMH;        // 64
    float* scb   = su + 64;              // 8
    float* sq    = scb + 8;              // [tr][68] (32 token-rows)
    float* sk    = sq + 32 * SW;
    float* stokA = sk + 32 * SW;         // buffer 0
    constexpr int SROWS = (QOFF == KVOFF) ? 32 : 64;
    float* stokB = stokA + SROWS * SWT;  // buffer 1

    const int tid  = threadIdx.x;
    const int w    = tid >> 5, lane = tid & 31;
    const int kl   = lane & 15, sg = lane >> 4;
    const int eh   = w & 1;              // 0 = Q, 1 = K
    const int rgw  = w >> 1;
    const int tr0  = rgw * 8 + sg * 4;

    constexpr bool SELF = (QOFF == KVOFF);
    constexpr int FOFF = POOLB ? 64 : 0;
    const int NT = BB / 8;

    for (int i = tid; i < 128 * 64; i += 256) {
        int e = i >> 6, c = i & 63;
        sWqk[e * SW + c] = Win[i];
    }
    if (tid < 128) sbqk[tid] = bin[tid];

    // u_c = sum_e Wf[FOFF+e] * Wo[e][c]
    if (tid < 64) {
        float s = 0.f;
        for (int e = 0; e < 64; e++) s = fmaf(Wf[FOFF + e], Wo[e * 64 + tid], s);
        su[tid] = s;
    }
    __syncthreads();

    // m_h[c] = sum_{cc in head h} u_cc * Wv[cc][c]
    {
        int h = tid >> 6, dd2 = tid & 63;
        float s = 0.f;
        #pragma unroll
        for (int cc = 0; cc < 16; cc++)
            s = fmaf(su[h * 16 + cc], Win[(128 + h * 16 + cc) * 64 + dd2], s);
        smh[h * SMH + dd2] = s;
    }
    if (tid == 0) {
        float s = 0.f;
        for (int c = 0; c < 64; c++) s = fmaf(su[c], bin[128 + c], s);
        scb[0] = 0.5f * s;
    }

    // staging issue: tile t -> buffer buf (cp.async, 16B each)
    auto issue = [&](int t, float* buf) {
        const int r0 = t * 8;
        if (SELF) {
            #pragma unroll
            for (int i2 = 0; i2 < 2; i2++) {
                int i = tid + 256 * i2;          // 0..511 float4s
                int trow = i >> 4, c4 = i & 15;  // trow = br*4+tk
                int br = trow >> 2, tk = trow & 3;
                cpa16(buf + trow * SWT + c4 * 4,
                      g_tok + (r0 + br) * 512 + (QOFF + tk) * 64 + c4 * 4);
            }
        } else {
            #pragma unroll
            for (int i2 = 0; i2 < 4; i2++) {
                int i = tid + 256 * i2;          // 0..1023 float4s (linear)
                int trow = i >> 4, c4 = i & 15;
                cpa16(buf + trow * SWT + c4 * 4, g_tok + r0 * 512 + i * 4);
            }
        }
    };

    // prologue: prefetch first tile into buffer A
    if (blockIdx.x < NT) issue(blockIdx.x, stokA);
    CP_COMMIT();

    int parity = 0;
    for (int t = blockIdx.x; t < NT; t += gridDim.x) {
        const int r0 = t * 8;
        float* cur = parity ? stokB : stokA;
        float* nxt = parity ? stokA : stokB;

        __syncthreads();                 // prev tile compute done (nxt free)
        int tn = t + gridDim.x;
        if (tn < NT) issue(tn, nxt);
        CP_COMMIT();
        CP_WAIT1();                      // cur tile's group has landed
        __syncthreads();

        // ---- Q/K proj: thread = 4 token-rows x 4 outputs ------------------
        {
            ull acc[4][4];
            #pragma unroll
            for (int i = 0; i < 4; i++)
                #pragma unroll
                for (int s = 0; s < 4; s++)
                    acc[i][s] = pk2(sbqk[kl + 16 * s + 64 * eh], 0.f);

            const int off = eh ? KVOFF : QOFF;
            const float* ap[4];
            #pragma unroll
            for (int i = 0; i < 4; i++) {
                int tr = tr0 + i;
                int row;
                if (SELF) row = tr;
                else      row = (tr >> 2) * 8 + off + (tr & 3);
                ap[i] = cur + row * SWT;
            }
            const float* bp = sWqk + (kl + 64 * eh) * SW;

            #pragma unroll 2
            for (int c = 0; c < 64; c += 4) {
                ulonglong2 bv[4];
                #pragma unroll
                for (int s = 0; s < 4; s++) bv[s] = ld4(bp + s * 16 * SW + c);
                #pragma unroll
                for (int i = 0; i < 4; i++) {
                    ulonglong2 av = ld4(ap[i] + c);
                    #pragma unroll
                    for (int s = 0; s < 4; s++) {
                        acc[i][s] = ffma2(av.x, bv[s].x, acc[i][s]);
                        acc[i][s] = ffma2(av.y, bv[s].y, acc[i][s]);
                    }
                }
            }
            float* dest = eh ? sk : sq;
            #pragma unroll
            for (int i = 0; i < 4; i++) {
                int trw = (tr0 + i) * SW;
                #pragma unroll
                for (int s = 0; s < 4; s++) {
                    float2 p = upk(acc[i][s]);
                    dest[trw + kl + 16 * s] = p.x + p.y;
                }
            }
        }
        __syncthreads();

        // ---- attention + folded pooling: warp w -> batch row w ------------
        {
            const int br = w;
            const float* sq_r = sq + br * 4 * SW;
            const float* sk_r = sk + br * 4 * SW;

            float a01[2];
            #pragma unroll
            for (int z = 0; z < 2; z++) {
                int m = lane + 32 * z;
                int h = m >> 4, i = (m >> 2) & 3, j = m & 3;
                const float* qb = sq_r + i * SW + h * 16;
                const float* kb = sk_r + j * SW + h * 16;
                ull acc = 0ull;
                #pragma unroll
                for (int dd2 = 0; dd2 < 16; dd2 += 4) {
                    ulonglong2 qv = ld4(qb + dd2);
                    ulonglong2 kv = ld4(kb + dd2);
                    acc = ffma2(qv.x, kv.x, acc);
                    acc = ffma2(qv.y, kv.y, acc);
                }
                float2 p = upk(acc);
                a01[z] = (p.x + p.y) * 0.25f;
            }
            float m0 = a01[0], m1 = a01[1];
            m0 = fmaxf(m0, __shfl_xor_sync(0xffffffffu, m0, 1));
            m0 = fmaxf(m0, __shfl_xor_sync(0xffffffffu, m0, 2));
            m1 = fmaxf(m1, __shfl_xor_sync(0xffffffffu, m1, 1));
            m1 = fmaxf(m1, __shfl_xor_sync(0xffffffffu, m1, 2));
            float e0 = __expf(a01[0] - m0), e1 = __expf(a01[1] - m1);
            float s0 = e0, s1 = e1;
            s0 += __shfl_xor_sync(0xffffffffu, s0, 1);
            s0 += __shfl_xor_sync(0xffffffffu, s0, 2);
            s1 += __shfl_xor_sync(0xffffffffu, s1, 1);
            s1 += __shfl_xor_sync(0xffffffffu, s1, 2);
            float p0 = __fdividef(e0, s0);     // att for m = lane    (h 0..1)
            float p1 = __fdividef(e1, s1);     // att for m = lane+32 (h 2..3)

            // i-sums via shuffles
            float w0 = p0 + __shfl_xor_sync(0xffffffffu, p0, 4);
            w0 += __shfl_xor_sync(0xffffffffu, w0, 8);
            float w1 = p1 + __shfl_xor_sync(0xffffffffu, p1, 4);
            w1 += __shfl_xor_sync(0xffffffffu, w1, 8);

            // pool: lanes 0..15 hold (h = lane>>2, j = lane&3)
            int h = lane >> 2, j = lane & 3;
            int src = (h & 1) * 16 + j;
            float wa  = __shfl_sync(0xffffffffu, w0, src);
            float wbv = __shfl_sync(0xffffffffu, w1, src);
            float wbar = (h < 2) ? wa : wbv;

            float part = 0.f;
            {
                int kvrow = SELF ? (br * 4 + j) : (br * 8 + KVOFF + j);
                const float* mh = smh + h * SMH;
                const float* tj = cur + kvrow * SWT;
                ull acc = 0ull;
                #pragma unroll
                for (int c = 0; c < 64; c += 4) {
                    ulonglong2 mv = ld4(mh + c);
                    ulonglong2 tv = ld4(tj + c);
                    acc = ffma2(mv.x, tv.x, acc);
                    acc = ffma2(mv.y, tv.y, acc);
                }
                float2 p = upk(acc);
                part = wbar * (p.x + p.y);
                if (lane >= 16) part = 0.f;
            }
            part += __shfl_down_sync(0xffffffffu, part, 8);
            part += __shfl_down_sync(0xffffffffu, part, 4);
            part += __shfl_down_sync(0xffffffffu, part, 2);
            part += __shfl_down_sync(0xffffffffu, part, 1);
            if (lane == 0) {
                float S = 0.125f * part + scb[0];
                if (ACCUM) g_S[r0 + br] += S;
                else       g_S[r0 + br]  = S;
            }
        }
        parity ^= 1;
    }
}

// ---------------- epilogue: out = leaky(S + C) ------------------------------
__global__ __launch_bounds__(256)
void epi_kernel(const float* __restrict__ Wf, const float* __restrict__ bf,
                const float* __restrict__ bo_sa, const float* __restrict__ bo_sb,
                const float* __restrict__ bo_ca, const float* __restrict__ bo_cb,
                float* __restrict__ out)
{
    int b = blockIdx.x * blockDim.x + threadIdx.x;
    if (b >= BB) return;
    float C = bf[0];
    #pragma unroll 4
    for (int e = 0; e < 64; e++) {
        C = fmaf(0.5f * Wf[e],      bo_sa[e] + bo_ca[e], C);
        C = fmaf(0.5f * Wf[64 + e], bo_sb[e] + bo_cb[e], C);
    }
    float s = g_S[b] + C;
    out[b] = (s > 0.f) ? s : 0.01f * s;
}

// ---------------- launch ----------------------------------------------------
static const int A_SMEM   = TOK_SMEM_F * 4;
static const int M_SMEM_S = MHA_SELF_F * 4;
static const int M_SMEM_C = MHA_CROSS_F * 4;

extern "C" void kernel_launch(void* const* d_in, const int* in_sizes, int n_in,
                              void* d_out, int out_size)
{
    (void)in_sizes; (void)n_in; (void)out_size;
    const float* x  = (const float*)d_in[0];
    const float* w1 = (const float*)d_in[1];
    const float* b1 = (const float*)d_in[2];
    const float* w2 = (const float*)d_in[3];
    const float* b2 = (const float*)d_in[4];
    const float* w3 = (const float*)d_in[5];
    const float* b3 = (const float*)d_in[6];
    const float* Win_sa = (const float*)d_in[7];
    const float* bin_sa = (const float*)d_in[8];
    const float* Wo_sa  = (const float*)d_in[9];
    const float* bo_sa  = (const float*)d_in[10];
    const float* Win_sb = (const float*)d_in[11];
    const float* bin_sb = (const float*)d_in[12];
    const float* Wo_sb  = (const float*)d_in[13];
    const float* bo_sb  = (const float*)d_in[14];
    const float* Win_ca = (const float*)d_in[15];
    const float* bin_ca = (const float*)d_in[16];
    const float* Wo_ca  = (const float*)d_in[17];
    const float* bo_ca  = (const float*)d_in[18];
    const float* Win_cb = (const float*)d_in[19];
    const float* bin_cb = (const float*)d_in[20];
    const float* Wo_cb  = (const float*)d_in[21];
    const float* bo_cb  = (const float*)d_in[22];
    const float* Wf = (const float*)d_in[23];
    const float* bf = (const float*)d_in[24];
    float* out = (float*)d_out;

    cudaFuncSetAttribute(tok_kernel, cudaFuncAttributeMaxDynamicSharedMemorySize, A_SMEM);
    cudaFuncSetAttribute(mha_kernel<0, 0, false, false>, cudaFuncAttributeMaxDynamicSharedMemorySize, M_SMEM_S);
    cudaFuncSetAttribute(mha_kernel<4, 4, true,  true>,  cudaFuncAttributeMaxDynamicSharedMemorySize, M_SMEM_S);
    cudaFuncSetAttribute(mha_kernel<0, 4, true,  false>, cudaFuncAttributeMaxDynamicSharedMemorySize, M_SMEM_C);
    cudaFuncSetAttribute(mha_kernel<4, 0, true,  true>,  cudaFuncAttributeMaxDynamicSharedMemorySize, M_SMEM_C);

    tok_kernel<<<dim3(37, 8), 512, A_SMEM>>>(x, w1, b1, w2, b2, w3, b3);

    mha_kernel<0, 0, false, false><<<296, 256, M_SMEM_S>>>(Win_sa, bin_sa, Wo_sa, Wf);
    mha_kernel<4, 4, true,  true ><<<296, 256, M_SMEM_S>>>(Win_sb, bin_sb, Wo_sb, Wf);
    mha_kernel<0, 4, true,  false><<<296, 256, M_SMEM_C>>>(Win_ca, bin_ca, Wo_ca, Wf);
    mha_kernel<4, 0, true,  true ><<<296, 256, M_SMEM_C>>>(Win_cb, bin_cb, Wo_cb, Wf);

    epi_kernel<<<BB / 256, 256>>>(Wf, bf, bo_sa, bo_sb, bo_ca, bo_cb, out);
}